// round 1
// baseline (speedup 1.0000x reference)
#include <cuda_runtime.h>
#include <cuda_bf16.h>
#include <math.h>

// Problem constants
#define BB   4
#define SS   2048
#define DD   1024          // D_IN == D_OUT
#define BM   64
#define BN   64
#define BK   32

// ---------------------------------------------------------------------------
// Scratch (static device allocations are the allowed scratch mechanism)
// ---------------------------------------------------------------------------
__device__ float g_Q[(long long)BB * SS * DD];           // 32 MB
__device__ float g_K[(long long)BB * SS * DD];           // 32 MB
__device__ float g_V[(long long)BB * SS * DD];           // 32 MB
__device__ float g_S[(long long)BB * SS * SS];           // 64 MB scores / probs

// ---------------------------------------------------------------------------
// Generic 64x64 tiled fp32 GEMM.
//   C[m,n] (+batch z) = alpha * sum_k A[m,k] * B'[k,n]
//   TRANS_B:    B stored as [N,K] row-major (used for Q @ K^T)
//   MASK_A:     zero A[m,k] where global k > global m (causal mask on P)
//   TRIANGULAR: skip tiles with blockIdx.x > blockIdx.y (scores upper tri)
//   PER_QTILE_K: K limit = (blockIdx.y+1)*BM (P@V only needs k <= q range)
// All dims are multiples of the tile sizes for this problem; no edge handling.
// ---------------------------------------------------------------------------
template<bool TRANS_B, bool MASK_A, bool TRIANGULAR, bool PER_QTILE_K>
__global__ void __launch_bounds__(256)
gemm_tile(const float* __restrict__ A, int lda, long long strideA,
          const float* __restrict__ B, int ldb, long long strideB,
          float* __restrict__ C, int ldc, long long strideC,
          int Kfull, float alpha)
{
    if (TRIANGULAR && blockIdx.x > blockIdx.y) return;

    const int bz = blockIdx.z;
    A += strideA * bz;
    B += strideB * bz;
    C += strideC * bz;

    const int m0 = blockIdx.y * BM;
    const int n0 = blockIdx.x * BN;
    const int Klim = PER_QTILE_K ? (int)(blockIdx.y + 1) * BM : Kfull;

    __shared__ float As[BK][BM + 4];   // row stride 68 floats = 272B (16B-mult)
    __shared__ float Bs[BK][BN + 4];

    const int tid = threadIdx.x;
    const int tx = tid & 15;           // n micro-tile index
    const int ty = tid >> 4;           // m micro-tile index

    float acc[4][4] = {};

    for (int k0 = 0; k0 < Klim; k0 += BK) {
        // ---- load A tile (64 rows x 32 k), stored transposed As[k][m] ----
        #pragma unroll
        for (int t = 0; t < 2; t++) {
            int f   = tid + t * 256;           // 0..511 float4 slots
            int row = f >> 3;                  // m within tile
            int c4  = f & 7;                   // k float4 chunk
            const float4 va = *reinterpret_cast<const float4*>(
                &A[(long long)(m0 + row) * lda + k0 + c4 * 4]);
            float vv[4] = {va.x, va.y, va.z, va.w};
            #pragma unroll
            for (int j = 0; j < 4; j++) {
                float xval = vv[j];
                if (MASK_A) {
                    int gcol = k0 + c4 * 4 + j;
                    int grow = m0 + row;
                    if (gcol > grow) xval = 0.0f;   // select, never multiply
                }
                As[c4 * 4 + j][row] = xval;
            }
        }
        // ---- load B tile, stored Bs[k][n] ----
        if (TRANS_B) {
            // B is [N,K] row-major: load 64 n-rows x 32 k, transpose like A
            #pragma unroll
            for (int t = 0; t < 2; t++) {
                int f   = tid + t * 256;
                int row = f >> 3;              // n within tile
                int c4  = f & 7;               // k float4 chunk
                const float4 vb = *reinterpret_cast<const float4*>(
                    &B[(long long)(n0 + row) * ldb + k0 + c4 * 4]);
                Bs[c4 * 4 + 0][row] = vb.x;
                Bs[c4 * 4 + 1][row] = vb.y;
                Bs[c4 * 4 + 2][row] = vb.z;
                Bs[c4 * 4 + 3][row] = vb.w;
            }
        } else {
            // B is [K,N] row-major: direct vectorized copy
            #pragma unroll
            for (int t = 0; t < 2; t++) {
                int f   = tid + t * 256;
                int row = f >> 4;              // k within tile
                int c4  = f & 15;              // n float4 chunk
                const float4 vb = *reinterpret_cast<const float4*>(
                    &B[(long long)(k0 + row) * ldb + n0 + c4 * 4]);
                *reinterpret_cast<float4*>(&Bs[row][c4 * 4]) = vb;
            }
        }
        __syncthreads();

        // ---- 16 FMA per thread per k ----
        #pragma unroll
        for (int kk = 0; kk < BK; kk++) {
            float4 a4 = *reinterpret_cast<const float4*>(&As[kk][ty * 4]);
            float4 b4 = *reinterpret_cast<const float4*>(&Bs[kk][tx * 4]);
            float a[4] = {a4.x, a4.y, a4.z, a4.w};
            float b[4] = {b4.x, b4.y, b4.z, b4.w};
            #pragma unroll
            for (int i = 0; i < 4; i++)
                #pragma unroll
                for (int j = 0; j < 4; j++)
                    acc[i][j] = fmaf(a[i], b[j], acc[i][j]);
        }
        __syncthreads();
    }

    #pragma unroll
    for (int i = 0; i < 4; i++) {
        float4 o;
        o.x = acc[i][0] * alpha;
        o.y = acc[i][1] * alpha;
        o.z = acc[i][2] * alpha;
        o.w = acc[i][3] * alpha;
        *reinterpret_cast<float4*>(
            &C[(long long)(m0 + ty * 4 + i) * ldc + n0 + tx * 4]) = o;
    }
}

// ---------------------------------------------------------------------------
// Row softmax over k in [0, q] (causal). One block per (b,q) row.
// Entries beyond q are never read and never written (P@V masks them at load).
// ---------------------------------------------------------------------------
__global__ void __launch_bounds__(256)
softmax_causal(float* __restrict__ P)
{
    const int row = blockIdx.x;                  // b*S + q
    const int q   = row & (SS - 1);              // S is power of two
    const int n   = q + 1;
    float* p = P + (long long)row * SS;

    const int tid = threadIdx.x;
    float v[8];
    float mx = -INFINITY;
    #pragma unroll
    for (int i = 0; i < 8; i++) {
        int idx = i * 256 + tid;
        v[i] = (idx < n) ? p[idx] : -INFINITY;
        mx = fmaxf(mx, v[i]);
    }

    __shared__ float red[256];
    red[tid] = mx;
    __syncthreads();
    #pragma unroll
    for (int s = 128; s > 0; s >>= 1) {
        if (tid < s) red[tid] = fmaxf(red[tid], red[tid + s]);
        __syncthreads();
    }
    mx = red[0];
    __syncthreads();

    float e[8];
    float sum = 0.0f;
    #pragma unroll
    for (int i = 0; i < 8; i++) {
        e[i] = __expf(v[i] - mx);                // -inf -> 0
        sum += e[i];
    }
    red[tid] = sum;
    __syncthreads();
    #pragma unroll
    for (int s = 128; s > 0; s >>= 1) {
        if (tid < s) red[tid] += red[tid + s];
        __syncthreads();
    }
    const float inv = 1.0f / red[0];

    #pragma unroll
    for (int i = 0; i < 8; i++) {
        int idx = i * 256 + tid;
        if (idx < n) p[idx] = e[i] * inv;
    }
}

// ---------------------------------------------------------------------------
// Launch: QKV GEMMs -> causal scores -> softmax -> P@V. Graph-capturable:
// kernel launches only, no allocation, no sync.
// ---------------------------------------------------------------------------
extern "C" void kernel_launch(void* const* d_in, const int* in_sizes, int n_in,
                              void* d_out, int out_size)
{
    const float* x  = (const float*)d_in[0];
    const float* Wq = (const float*)d_in[1];
    const float* Wk = (const float*)d_in[2];
    const float* Wv = (const float*)d_in[3];
    float* out = (float*)d_out;

    float *Q, *K, *V, *Sb;
    cudaGetSymbolAddress((void**)&Q,  g_Q);
    cudaGetSymbolAddress((void**)&K,  g_K);
    cudaGetSymbolAddress((void**)&V,  g_V);
    cudaGetSymbolAddress((void**)&Sb, g_S);

    const long long sQKV = (long long)SS * DD;     // per-batch Q/K/V stride
    const long long sSco = (long long)SS * SS;     // per-batch scores stride
    const float scale = 0.03125f;                  // 1024^-0.5

    // 1) QKV projections: [8192,1024] @ [1024,1024]
    dim3 gq(DD / BN, (BB * SS) / BM, 1);
    gemm_tile<false,false,false,false><<<gq, 256>>>(x, DD, 0, Wq, DD, 0, Q, DD, 0, DD, 1.0f);
    gemm_tile<false,false,false,false><<<gq, 256>>>(x, DD, 0, Wk, DD, 0, K, DD, 0, DD, 1.0f);
    gemm_tile<false,false,false,false><<<gq, 256>>>(x, DD, 0, Wv, DD, 0, V, DD, 0, DD, 1.0f);

    // 2) Scores = scale * Q @ K^T, lower-triangular tiles only
    dim3 gs(SS / BN, SS / BM, BB);
    gemm_tile<true,false,true,false><<<gs, 256>>>(Q, DD, sQKV, K, DD, sQKV,
                                                  Sb, SS, sSco, DD, scale);

    // 3) Causal softmax in place
    softmax_causal<<<BB * SS, 256>>>(Sb);

    // 4) Out = P @ V with per-q-tile K range + diagonal-tile masking
    dim3 gp(DD / BN, SS / BM, BB);
    gemm_tile<false,true,false,true><<<gp, 256>>>(Sb, SS, sSco, V, DD, sQKV,
                                                  out, DD, sQKV, 0, 1.0f);
}

// round 3
// speedup vs baseline: 1.8484x; 1.8484x over previous
#include <cuda_runtime.h>
#include <cuda_bf16.h>
#include <cstdint>
#include <math.h>

#define BB 4
#define SS 2048
#define DD 1024

#define TM 128
#define TN 128
#define TK 32
#define NTHREADS 512

#define DSM_BYTES (65536 + 1024)

// ---------------------------------------------------------------------------
// Scratch (__device__ globals: allocation-guard-safe)
// ---------------------------------------------------------------------------
__device__ float g_Q [(size_t)BB * SS * DD];          // 32 MB
__device__ float g_K [(size_t)BB * SS * DD];          // 32 MB
__device__ float g_V [(size_t)BB * SS * DD];          // 32 MB
__device__ float g_Vt[(size_t)BB * SS * DD];          // 32 MB  V^T per batch
__device__ float g_S [(size_t)BB * SS * SS];          // 64 MB  scores/probs
__device__ float g_Wt[3][(size_t)DD * DD];            // 12 MB  W^T (K-major B)

// ---------------------------------------------------------------------------
// Helpers
// ---------------------------------------------------------------------------
__device__ __forceinline__ uint32_t smem_u32(const void* p) {
    uint32_t a;
    asm("{ .reg .u64 t; cvta.to.shared.u64 t, %1; cvt.u32.u64 %0, t; }"
        : "=r"(a) : "l"(p));
    return a;
}

// SW64-style swizzle for 64-byte rows: XOR 16B-unit bits [5:4] with row bits.
#define SWZ(o) ((uint32_t)(o) ^ ((((uint32_t)(o)) >> 3) & 0x30u))

#define LDSM4(r, a)                                                        \
    asm volatile("ldmatrix.sync.aligned.m8n8.x4.shared.b16 "               \
                 "{%0,%1,%2,%3}, [%4];"                                    \
                 : "=r"((r)[0]), "=r"((r)[1]), "=r"((r)[2]), "=r"((r)[3])  \
                 : "r"(a))

#define MMA16816(d, a, b0, b1)                                             \
    asm volatile("mma.sync.aligned.m16n8k16.row.col.f32.bf16.bf16.f32 "    \
                 "{%0,%1,%2,%3},{%4,%5,%6,%7},{%8,%9},{%0,%1,%2,%3};"      \
                 : "+f"((d)[0]), "+f"((d)[1]), "+f"((d)[2]), "+f"((d)[3])  \
                 : "r"((a)[0]), "r"((a)[1]), "r"((a)[2]), "r"((a)[3]),     \
                   "r"(b0), "r"(b1))

__device__ __forceinline__ uint32_t pack2(__nv_bfloat16 a, __nv_bfloat16 b) {
    uint16_t ua = *reinterpret_cast<uint16_t*>(&a);
    uint16_t ub = *reinterpret_cast<uint16_t*>(&b);
    return (uint32_t)ua | ((uint32_t)ub << 16);
}

// fp32x4 -> (bf16 hi x4, bf16 lo x4), stored as two 8B smem writes
__device__ __forceinline__ void cvt_store(uint32_t hiA, uint32_t loA, float4 v) {
    __nv_bfloat16 hx = __float2bfloat16_rn(v.x);
    __nv_bfloat16 hy = __float2bfloat16_rn(v.y);
    __nv_bfloat16 hz = __float2bfloat16_rn(v.z);
    __nv_bfloat16 hw = __float2bfloat16_rn(v.w);
    uint32_t w0 = pack2(hx, hy), w1 = pack2(hz, hw);
    float rx = v.x - __bfloat162float(hx);
    float ry = v.y - __bfloat162float(hy);
    float rz = v.z - __bfloat162float(hz);
    float rw = v.w - __bfloat162float(hw);
    uint32_t l0 = pack2(__float2bfloat16_rn(rx), __float2bfloat16_rn(ry));
    uint32_t l1 = pack2(__float2bfloat16_rn(rz), __float2bfloat16_rn(rw));
    asm volatile("st.shared.v2.b32 [%0], {%1,%2};"
                 :: "r"(hiA), "r"(w0), "r"(w1) : "memory");
    asm volatile("st.shared.v2.b32 [%0], {%1,%2};"
                 :: "r"(loA), "r"(l0), "r"(l1) : "memory");
}

// ---------------------------------------------------------------------------
// Split-bf16 mma.sync GEMM.  C[m,n] = alpha * sum_k A[m,k] * B[n,k]
// (B stored K-major: [N rows][K cols] row-major.)
//   TRI : skip tiles with bx > by (causal scores)
//   PERQ: K limit = (by+1)*TM (P@V per-q-tile range)
// Dyn smem: two buffers x { Ah(8K) Al(8K) Bh(8K) Bl(8K) } = 64KB (+align)
// ---------------------------------------------------------------------------
template<bool TRI, bool PERQ>
__global__ void __launch_bounds__(NTHREADS)
mma_gemm(const float* __restrict__ A, int lda, long long sA,
         const float* __restrict__ B, int ldb, long long sB,
         float* __restrict__ C, int ldc, long long sC,
         int Kfull, float alpha)
{
    if (TRI && blockIdx.x > blockIdx.y) return;

    extern __shared__ char dsm[];
    const uint32_t sbase = (smem_u32(dsm) + 1023u) & ~1023u;

    A += sA * blockIdx.z; B += sB * blockIdx.z; C += sC * blockIdx.z;
    const int m0 = blockIdx.y * TM;
    const int n0 = blockIdx.x * TN;
    const int Klim = PERQ ? (int)(blockIdx.y + 1) * TM : Kfull;
    const int KB = Klim / TK;

    const int tid  = threadIdx.x;
    const int lane = tid & 31;
    const int wid  = tid >> 5;
    const int wm = (wid & 3) * 32;      // warp m offset in tile
    const int wn = (wid >> 2) * 32;     // warp n offset in tile

    // ldmatrix lane offsets (tile-relative, swizzled, for k16 chunk c=0).
    // lanes 0-7: rows +0..7 (k0-7); 8-15: rows +8..15 (k0-7);
    // 16-23: rows +0..7 (k8-15); 24-31: rows +8..15 (k8-15).
    uint32_t aOff[2], bOff[2];
    {
        const int r  = lane & 15;
        const int hb = (lane >> 4) * 16;
        aOff[0] = SWZ((wm +      r) * 64 + hb);
        aOff[1] = SWZ((wm + 16 + r) * 64 + hb);
        bOff[0] = SWZ((wn +      r) * 64 + hb);
        bOff[1] = SWZ((wn + 16 + r) * 64 + hb);
    }

    // staging-load / convert-store coordinates (2 float4 per thread per tile)
    int ldRow[2], ldC4[2];
    uint32_t stOff[2];
#pragma unroll
    for (int i = 0; i < 2; i++) {
        int f = tid + i * NTHREADS;
        ldRow[i] = f >> 3;
        ldC4[i]  = f & 7;
        stOff[i] = SWZ(ldRow[i] * 64 + ldC4[i] * 8);
    }

    float acc[2][4][4];
#pragma unroll
    for (int mf = 0; mf < 2; mf++)
#pragma unroll
        for (int nf = 0; nf < 4; nf++)
#pragma unroll
            for (int j = 0; j < 4; j++) acc[mf][nf][j] = 0.0f;

    float4 sa[2], sb[2];

    // ---- prologue: load + convert + store k-block 0 into buffer 0 ----
#pragma unroll
    for (int i = 0; i < 2; i++) {
        sa[i] = *reinterpret_cast<const float4*>(
            A + (long long)(m0 + ldRow[i]) * lda + ldC4[i] * 4);
        sb[i] = *reinterpret_cast<const float4*>(
            B + (long long)(n0 + ldRow[i]) * ldb + ldC4[i] * 4);
    }
#pragma unroll
    for (int i = 0; i < 2; i++) {
        cvt_store(sbase +         stOff[i], sbase +  8192 + stOff[i], sa[i]);
        cvt_store(sbase + 16384 + stOff[i], sbase + 24576 + stOff[i], sb[i]);
    }
    __syncthreads();

    for (int kb = 0; kb < KB; kb++) {
        const uint32_t buf = sbase + (uint32_t)(kb & 1) * 32768u;
        const bool more = (kb + 1 < KB);

        if (more) {
            const int k0 = (kb + 1) * TK;
#pragma unroll
            for (int i = 0; i < 2; i++) {
                sa[i] = *reinterpret_cast<const float4*>(
                    A + (long long)(m0 + ldRow[i]) * lda + k0 + ldC4[i] * 4);
                sb[i] = *reinterpret_cast<const float4*>(
                    B + (long long)(n0 + ldRow[i]) * ldb + k0 + ldC4[i] * 4);
            }
        }

        // ---- compute 2 k16 steps on current buffer ----
#pragma unroll
        for (int c = 0; c < 2; c++) {
            const uint32_t ko = (uint32_t)(c * 32);
            uint32_t ah[2][4], al[2][4], bh[2][4], bl[2][4];
            LDSM4(ah[0], buf +         (aOff[0] ^ ko));
            LDSM4(ah[1], buf +         (aOff[1] ^ ko));
            LDSM4(al[0], buf +  8192 + (aOff[0] ^ ko));
            LDSM4(al[1], buf +  8192 + (aOff[1] ^ ko));
            LDSM4(bh[0], buf + 16384 + (bOff[0] ^ ko));
            LDSM4(bh[1], buf + 16384 + (bOff[1] ^ ko));
            LDSM4(bl[0], buf + 24576 + (bOff[0] ^ ko));
            LDSM4(bl[1], buf + 24576 + (bOff[1] ^ ko));

#pragma unroll
            for (int mf = 0; mf < 2; mf++) {
#pragma unroll
                for (int nf = 0; nf < 4; nf++) {
                    const int g = nf >> 1, s = nf & 1;
                    MMA16816(acc[mf][nf], ah[mf], bh[g][s], bh[g][s + 2]);
                    MMA16816(acc[mf][nf], ah[mf], bl[g][s], bl[g][s + 2]);
                    MMA16816(acc[mf][nf], al[mf], bh[g][s], bh[g][s + 2]);
                }
            }
        }

        if (more) {
            const uint32_t nbuf = sbase + (uint32_t)((kb + 1) & 1) * 32768u;
#pragma unroll
            for (int i = 0; i < 2; i++) {
                cvt_store(nbuf +         stOff[i], nbuf +  8192 + stOff[i], sa[i]);
                cvt_store(nbuf + 16384 + stOff[i], nbuf + 24576 + stOff[i], sb[i]);
            }
        }
        __syncthreads();
    }

    // ---- epilogue ----
    const int g = lane >> 2, t = lane & 3;
#pragma unroll
    for (int mf = 0; mf < 2; mf++) {
#pragma unroll
        for (int nf = 0; nf < 4; nf++) {
            const int r0  = m0 + wm + 16 * mf + g;
            const int col = n0 + wn + 8 * nf + 2 * t;
            float2 v0, v1;
            v0.x = acc[mf][nf][0] * alpha;
            v0.y = acc[mf][nf][1] * alpha;
            v1.x = acc[mf][nf][2] * alpha;
            v1.y = acc[mf][nf][3] * alpha;
            *reinterpret_cast<float2*>(C + (long long)r0 * ldc + col)       = v0;
            *reinterpret_cast<float2*>(C + (long long)(r0 + 8) * ldc + col) = v1;
        }
    }
}

// ---------------------------------------------------------------------------
// Tiled transpose: out[c][r] = in[r][c], per-z batch (stride elements each)
// ---------------------------------------------------------------------------
__global__ void __launch_bounds__(256)
transpose32(const float* __restrict__ in, float* __restrict__ out,
            int R, int C, long long stride)
{
    __shared__ float t[32][33];
    in  += stride * blockIdx.z;
    out += stride * blockIdx.z;
    const int c0 = blockIdx.x * 32, r0 = blockIdx.y * 32;
#pragma unroll
    for (int j = threadIdx.y; j < 32; j += 8)
        t[j][threadIdx.x] = in[(long long)(r0 + j) * C + c0 + threadIdx.x];
    __syncthreads();
#pragma unroll
    for (int j = threadIdx.y; j < 32; j += 8)
        out[(long long)(c0 + j) * R + r0 + threadIdx.x] = t[threadIdx.x][j];
}

// ---------------------------------------------------------------------------
// Causal row softmax over k in [0,q]; zero-fills (q, 128-aligned block end)
// so the P@V tensor GEMM needs no masking.
// ---------------------------------------------------------------------------
__global__ void __launch_bounds__(256)
softmax_causal(float* __restrict__ P)
{
    const int row = blockIdx.x;          // b*S + q
    const int q   = row & (SS - 1);
    const int limit = ((q >> 7) + 1) << 7;
    float* p = P + (long long)row * SS;

    const int tid = threadIdx.x;
    float v[8];
    float mx = -INFINITY;
#pragma unroll
    for (int i = 0; i < 8; i++) {
        int idx = i * 256 + tid;
        v[i] = (idx <= q) ? p[idx] : -INFINITY;
        mx = fmaxf(mx, v[i]);
    }

    __shared__ float red[256];
    red[tid] = mx;
    __syncthreads();
#pragma unroll
    for (int s = 128; s > 0; s >>= 1) {
        if (tid < s) red[tid] = fmaxf(red[tid], red[tid + s]);
        __syncthreads();
    }
    mx = red[0];
    __syncthreads();

    float e[8];
    float sum = 0.0f;
#pragma unroll
    for (int i = 0; i < 8; i++) {
        e[i] = __expf(v[i] - mx);
        sum += e[i];
    }
    red[tid] = sum;
    __syncthreads();
#pragma unroll
    for (int s = 128; s > 0; s >>= 1) {
        if (tid < s) red[tid] += red[tid + s];
        __syncthreads();
    }
    const float inv = 1.0f / red[0];

#pragma unroll
    for (int i = 0; i < 8; i++) {
        int idx = i * 256 + tid;
        if (idx <= q)          p[idx] = e[i] * inv;
        else if (idx < limit)  p[idx] = 0.0f;
    }
}

// ---------------------------------------------------------------------------
// Launch sequence (graph-capturable: kernel launches only)
// ---------------------------------------------------------------------------
extern "C" void kernel_launch(void* const* d_in, const int* in_sizes, int n_in,
                              void* d_out, int out_size)
{
    const float* x  = (const float*)d_in[0];
    const float* Wq = (const float*)d_in[1];
    const float* Wk = (const float*)d_in[2];
    const float* Wv = (const float*)d_in[3];
    float* out = (float*)d_out;

    float *Q, *Kb, *V, *Vt, *Sb, *Wt;
    cudaGetSymbolAddress((void**)&Q,  g_Q);
    cudaGetSymbolAddress((void**)&Kb, g_K);
    cudaGetSymbolAddress((void**)&V,  g_V);
    cudaGetSymbolAddress((void**)&Vt, g_Vt);
    cudaGetSymbolAddress((void**)&Sb, g_S);
    cudaGetSymbolAddress((void**)&Wt, g_Wt);
    float* WtQ = Wt;
    float* WtK = Wt + (size_t)DD * DD;
    float* WtV = Wt + 2 * (size_t)DD * DD;

    cudaFuncSetAttribute(mma_gemm<false, false>,
                         cudaFuncAttributeMaxDynamicSharedMemorySize, DSM_BYTES);
    cudaFuncSetAttribute(mma_gemm<true, false>,
                         cudaFuncAttributeMaxDynamicSharedMemorySize, DSM_BYTES);
    cudaFuncSetAttribute(mma_gemm<false, true>,
                         cudaFuncAttributeMaxDynamicSharedMemorySize, DSM_BYTES);

    const long long sQKV = (long long)SS * DD;
    const long long sSco = (long long)SS * SS;
    const float scale = 0.03125f;     // 1024^-0.5

    // 0) W^T (K-major B operands)
    dim3 tb(32, 8);
    transpose32<<<dim3(DD / 32, DD / 32, 1), tb>>>(Wq, WtQ, DD, DD, 0);
    transpose32<<<dim3(DD / 32, DD / 32, 1), tb>>>(Wk, WtK, DD, DD, 0);
    transpose32<<<dim3(DD / 32, DD / 32, 1), tb>>>(Wv, WtV, DD, DD, 0);

    // 1) QKV projections: [8192,1024] x [1024,1024]
    dim3 gq(DD / TN, (BB * SS) / TM, 1);
    mma_gemm<false, false><<<gq, NTHREADS, DSM_BYTES>>>(x, DD, 0, WtQ, DD, 0, Q,  DD, 0, DD, 1.0f);
    mma_gemm<false, false><<<gq, NTHREADS, DSM_BYTES>>>(x, DD, 0, WtK, DD, 0, Kb, DD, 0, DD, 1.0f);
    mma_gemm<false, false><<<gq, NTHREADS, DSM_BYTES>>>(x, DD, 0, WtV, DD, 0, V,  DD, 0, DD, 1.0f);

    // 2) V^T per batch: [2048,1024] -> [1024,2048]
    transpose32<<<dim3(DD / 32, SS / 32, BB), tb>>>(V, Vt, SS, DD, sQKV);

    // 3) scores = scale * Q @ K^T (lower tiles only; K matrix already K-major)
    dim3 gs(SS / TN, SS / TM, BB);
    mma_gemm<true, false><<<gs, NTHREADS, DSM_BYTES>>>(Q, DD, sQKV, Kb, DD, sQKV,
                                                       Sb, SS, sSco, DD, scale);

    // 4) causal softmax (+ zero-fill to 128 boundary)
    softmax_causal<<<BB * SS, 256>>>(Sb);

    // 5) out = P @ V  (B = V^T K-major; K-range clamped per q-tile)
    dim3 gp(DD / TN, SS / TM, BB);
    mma_gemm<false, true><<<gp, NTHREADS, DSM_BYTES>>>(Sb, SS, sSco, Vt, SS, sQKV,
                                                       out, DD, sQKV, 0, 1.0f);
}

// round 4
// speedup vs baseline: 2.5771x; 1.3943x over previous
#include <cuda_runtime.h>
#include <cuda_bf16.h>
#include <cstdint>
#include <math.h>

#define BB 4
#define SS 2048
#define DD 1024

#define TM 128
#define TN 128
#define TK 32
#define NTHREADS 512
#define STAGES 4
#define STAGE_BYTES 32768
#define DSM_BYTES (STAGES * STAGE_BYTES + 1024)

typedef __nv_bfloat16 bf16;

// ---------------------------------------------------------------------------
// Scratch (__device__ globals: allocation-guard-safe)
// ---------------------------------------------------------------------------
__device__ bf16  g_Xh [(size_t)BB * SS * DD];         // x hi        16 MB
__device__ bf16  g_Xl [(size_t)BB * SS * DD];         // x lo        16 MB
__device__ bf16  g_Wth[3][(size_t)DD * DD];           // W^T hi       6 MB
__device__ bf16  g_Wtl[3][(size_t)DD * DD];           // W^T lo       6 MB
__device__ bf16  g_Qh [(size_t)BB * SS * DD];         // Q hi        16 MB
__device__ bf16  g_Ql [(size_t)BB * SS * DD];
__device__ bf16  g_Kh [(size_t)BB * SS * DD];
__device__ bf16  g_Kl [(size_t)BB * SS * DD];
__device__ float g_V  [(size_t)BB * SS * DD];         // V fp32      32 MB
__device__ bf16  g_Vth[(size_t)BB * SS * DD];         // V^T hi      16 MB
__device__ bf16  g_Vtl[(size_t)BB * SS * DD];
__device__ float g_S  [(size_t)BB * SS * SS];         // scores fp32 64 MB
__device__ bf16  g_Ph [(size_t)BB * SS * SS];         // probs hi    32 MB
__device__ bf16  g_Pl [(size_t)BB * SS * SS];         // probs lo    32 MB

// ---------------------------------------------------------------------------
// Helpers
// ---------------------------------------------------------------------------
__device__ __forceinline__ uint32_t smem_u32(const void* p) {
    uint32_t a;
    asm("{ .reg .u64 t; cvta.to.shared.u64 t, %1; cvt.u32.u64 %0, t; }"
        : "=r"(a) : "l"(p));
    return a;
}

// swizzle for 64-byte rows: XOR 16B-unit bits [5:4] with row bits [2:1]
#define SWZ(o) ((uint32_t)(o) ^ ((((uint32_t)(o)) >> 3) & 0x30u))

#define LDSM4(r, a)                                                        \
    asm volatile("ldmatrix.sync.aligned.m8n8.x4.shared.b16 "               \
                 "{%0,%1,%2,%3}, [%4];"                                    \
                 : "=r"((r)[0]), "=r"((r)[1]), "=r"((r)[2]), "=r"((r)[3])  \
                 : "r"(a))

#define MMA16816(d, a, b0, b1)                                             \
    asm volatile("mma.sync.aligned.m16n8k16.row.col.f32.bf16.bf16.f32 "    \
                 "{%0,%1,%2,%3},{%4,%5,%6,%7},{%8,%9},{%0,%1,%2,%3};"      \
                 : "+f"((d)[0]), "+f"((d)[1]), "+f"((d)[2]), "+f"((d)[3])  \
                 : "r"((a)[0]), "r"((a)[1]), "r"((a)[2]), "r"((a)[3]),     \
                   "r"(b0), "r"(b1))

#define CPA16(dst, src)                                                    \
    asm volatile("cp.async.cg.shared.global [%0], [%1], 16;"               \
                 :: "r"(dst), "l"(src))
#define CPA_COMMIT()  asm volatile("cp.async.commit_group;" ::: "memory")
#define CPA_WAIT2()   asm volatile("cp.async.wait_group 2;" ::: "memory")

__device__ __forceinline__ uint32_t pack2(bf16 a, bf16 b) {
    uint16_t ua = *reinterpret_cast<uint16_t*>(&a);
    uint16_t ub = *reinterpret_cast<uint16_t*>(&b);
    return (uint32_t)ua | ((uint32_t)ub << 16);
}

__device__ __forceinline__ void split1(float v, bf16& h, bf16& l) {
    h = __float2bfloat16_rn(v);
    l = __float2bfloat16_rn(v - __bfloat162float(h));
}

// ---------------------------------------------------------------------------
// Split-bf16 mma.sync GEMM with 4-stage cp.async pipeline.
//   C[m,n] = alpha * sum_k A[m,k] * B[n,k]   (both operands K-major bf16 hi/lo)
//   TRI : skip tiles with bx > by (causal scores)
//   PERQ: K limit = (by+1)*TM (P@V per-q-tile range)
//   SPLIT_OUT: write Ch/Cl bf16 hi/lo instead of fp32 Cf
// Stage layout: Ah(8K) Al(8K) Bh(8K) Bl(8K) = 32KB; 4 stages = 128KB
// ---------------------------------------------------------------------------
template<bool TRI, bool PERQ, bool SPLIT_OUT>
__global__ void __launch_bounds__(NTHREADS)
mma_gemm(const bf16* __restrict__ Ah, const bf16* __restrict__ Al,
         int lda, long long sA,
         const bf16* __restrict__ Bh, const bf16* __restrict__ Bl,
         int ldb, long long sB,
         float* __restrict__ Cf, bf16* __restrict__ Ch, bf16* __restrict__ Cl,
         int ldc, long long sC, int Kfull, float alpha)
{
    if (TRI && blockIdx.x > blockIdx.y) return;

    extern __shared__ char dsm[];
    const uint32_t sbase = (smem_u32(dsm) + 1023u) & ~1023u;

    const long long z = blockIdx.z;
    Ah += sA * z; Al += sA * z; Bh += sB * z; Bl += sB * z;

    const int m0 = blockIdx.y * TM;
    const int n0 = blockIdx.x * TN;
    const int Klim = PERQ ? (int)(blockIdx.y + 1) * TM : Kfull;
    const int KB = Klim / TK;

    const int tid  = threadIdx.x;
    const int lane = tid & 31;
    const int wid  = tid >> 5;
    const int wm = (wid & 3) * 32;
    const int wn = (wid >> 2) * 32;

    // cp.async coordinates: 512 threads cover 128 rows x 4 16B-chunks
    const int ldrow = tid >> 2, c4 = tid & 3;
    const uint32_t stoff = SWZ(ldrow * 64 + c4 * 16);
    const bf16* gAh = Ah + (long long)(m0 + ldrow) * lda + c4 * 8;
    const bf16* gAl = Al + (long long)(m0 + ldrow) * lda + c4 * 8;
    const bf16* gBh = Bh + (long long)(n0 + ldrow) * ldb + c4 * 8;
    const bf16* gBl = Bl + (long long)(n0 + ldrow) * ldb + c4 * 8;

    // ldmatrix lane offsets
    uint32_t aOff[2], bOff[2];
    {
        const int r  = lane & 15;
        const int hb = (lane >> 4) * 16;
        aOff[0] = SWZ((wm +      r) * 64 + hb);
        aOff[1] = SWZ((wm + 16 + r) * 64 + hb);
        bOff[0] = SWZ((wn +      r) * 64 + hb);
        bOff[1] = SWZ((wn + 16 + r) * 64 + hb);
    }

    float acc[2][4][4];
#pragma unroll
    for (int mf = 0; mf < 2; mf++)
#pragma unroll
        for (int nf = 0; nf < 4; nf++)
#pragma unroll
            for (int j = 0; j < 4; j++) acc[mf][nf][j] = 0.0f;

    // ---- prologue: issue stages 0..2 ----
#pragma unroll
    for (int s = 0; s < STAGES - 1; s++) {
        if (s < KB) {
            const uint32_t sb = sbase + (uint32_t)s * STAGE_BYTES;
            const int k0 = s * TK;
            CPA16(sb +          stoff, gAh + k0);
            CPA16(sb +  8192u + stoff, gAl + k0);
            CPA16(sb + 16384u + stoff, gBh + k0);
            CPA16(sb + 24576u + stoff, gBl + k0);
        }
        CPA_COMMIT();
    }

    for (int kb = 0; kb < KB; kb++) {
        CPA_WAIT2();
        __syncthreads();

        // issue stage kb+3 (overwrites buffer computed at iter kb-1)
        if (kb + STAGES - 1 < KB) {
            const uint32_t sb = sbase + (uint32_t)((kb + STAGES - 1) & (STAGES - 1)) * STAGE_BYTES;
            const int k0 = (kb + STAGES - 1) * TK;
            CPA16(sb +          stoff, gAh + k0);
            CPA16(sb +  8192u + stoff, gAl + k0);
            CPA16(sb + 16384u + stoff, gBh + k0);
            CPA16(sb + 24576u + stoff, gBl + k0);
        }
        CPA_COMMIT();

        const uint32_t buf = sbase + (uint32_t)(kb & (STAGES - 1)) * STAGE_BYTES;
#pragma unroll
        for (int c = 0; c < 2; c++) {
            const uint32_t ko = (uint32_t)(c * 32);
            uint32_t ah[2][4], al[2][4], bh[2][4], bl[2][4];
            LDSM4(ah[0], buf +          (aOff[0] ^ ko));
            LDSM4(ah[1], buf +          (aOff[1] ^ ko));
            LDSM4(al[0], buf +  8192u + (aOff[0] ^ ko));
            LDSM4(al[1], buf +  8192u + (aOff[1] ^ ko));
            LDSM4(bh[0], buf + 16384u + (bOff[0] ^ ko));
            LDSM4(bh[1], buf + 16384u + (bOff[1] ^ ko));
            LDSM4(bl[0], buf + 24576u + (bOff[0] ^ ko));
            LDSM4(bl[1], buf + 24576u + (bOff[1] ^ ko));

#pragma unroll
            for (int mf = 0; mf < 2; mf++) {
#pragma unroll
                for (int nf = 0; nf < 4; nf++) {
                    const int g = nf >> 1, s = nf & 1;
                    MMA16816(acc[mf][nf], ah[mf], bh[g][s], bh[g][s + 2]);
                    MMA16816(acc[mf][nf], ah[mf], bl[g][s], bl[g][s + 2]);
                    MMA16816(acc[mf][nf], al[mf], bh[g][s], bh[g][s + 2]);
                }
            }
        }
    }

    // ---- epilogue ----
    const int g = lane >> 2, t = lane & 3;
    Cf += sC * z;
    Ch += sC * z;
    Cl += sC * z;
#pragma unroll
    for (int mf = 0; mf < 2; mf++) {
#pragma unroll
        for (int nf = 0; nf < 4; nf++) {
            const int r0  = m0 + wm + 16 * mf + g;
            const int col = n0 + wn + 8 * nf + 2 * t;
            float v0 = acc[mf][nf][0] * alpha;
            float v1 = acc[mf][nf][1] * alpha;
            float v2 = acc[mf][nf][2] * alpha;
            float v3 = acc[mf][nf][3] * alpha;
            if (SPLIT_OUT) {
                bf16 h0, l0, h1, l1, h2, l2, h3, l3;
                split1(v0, h0, l0); split1(v1, h1, l1);
                split1(v2, h2, l2); split1(v3, h3, l3);
                *reinterpret_cast<uint32_t*>(Ch + (long long)r0 * ldc + col)       = pack2(h0, h1);
                *reinterpret_cast<uint32_t*>(Cl + (long long)r0 * ldc + col)       = pack2(l0, l1);
                *reinterpret_cast<uint32_t*>(Ch + (long long)(r0 + 8) * ldc + col) = pack2(h2, h3);
                *reinterpret_cast<uint32_t*>(Cl + (long long)(r0 + 8) * ldc + col) = pack2(l2, l3);
            } else {
                float2 a0, a1;
                a0.x = v0; a0.y = v1; a1.x = v2; a1.y = v3;
                *reinterpret_cast<float2*>(Cf + (long long)r0 * ldc + col)       = a0;
                *reinterpret_cast<float2*>(Cf + (long long)(r0 + 8) * ldc + col) = a1;
            }
        }
    }
}

// ---------------------------------------------------------------------------
// fp32 -> split bf16 hi/lo elementwise (vectorized x4)
// ---------------------------------------------------------------------------
__global__ void __launch_bounds__(256)
convert_split(const float* __restrict__ in, bf16* __restrict__ oh,
              bf16* __restrict__ ol, int n4)
{
    int i = blockIdx.x * 256 + threadIdx.x;
    if (i >= n4) return;
    float4 v = reinterpret_cast<const float4*>(in)[i];
    bf16 h0, l0, h1, l1, h2, l2, h3, l3;
    split1(v.x, h0, l0); split1(v.y, h1, l1);
    split1(v.z, h2, l2); split1(v.w, h3, l3);
    reinterpret_cast<uint32_t*>(oh)[2 * i]     = pack2(h0, h1);
    reinterpret_cast<uint32_t*>(oh)[2 * i + 1] = pack2(h2, h3);
    reinterpret_cast<uint32_t*>(ol)[2 * i]     = pack2(l0, l1);
    reinterpret_cast<uint32_t*>(ol)[2 * i + 1] = pack2(l2, l3);
}

// ---------------------------------------------------------------------------
// fp32 [R x C] -> transposed split bf16 hi/lo [C x R] (per-z batch)
// ---------------------------------------------------------------------------
__global__ void __launch_bounds__(256)
transpose_split(const float* __restrict__ in, bf16* __restrict__ oh,
                bf16* __restrict__ ol, int R, int C,
                long long sIn, long long sOut)
{
    __shared__ float t[32][33];
    in += sIn * blockIdx.z;
    oh += sOut * blockIdx.z;
    ol += sOut * blockIdx.z;
    const int c0 = blockIdx.x * 32, r0 = blockIdx.y * 32;
#pragma unroll
    for (int j = threadIdx.y; j < 32; j += 8)
        t[j][threadIdx.x] = in[(long long)(r0 + j) * C + c0 + threadIdx.x];
    __syncthreads();
#pragma unroll
    for (int j = threadIdx.y; j < 32; j += 8) {
        float v = t[threadIdx.x][j];
        bf16 h, l;
        split1(v, h, l);
        oh[(long long)(c0 + j) * R + r0 + threadIdx.x] = h;
        ol[(long long)(c0 + j) * R + r0 + threadIdx.x] = l;
    }
}

// ---------------------------------------------------------------------------
// Causal row softmax: reads fp32 scores, writes split-bf16 probs;
// zero-fills (q, 128-aligned block end) so P@V needs no masking.
// ---------------------------------------------------------------------------
__global__ void __launch_bounds__(256)
softmax_causal(const float* __restrict__ S, bf16* __restrict__ Ph,
               bf16* __restrict__ Pl)
{
    const int row = blockIdx.x;          // b*S + q
    const int q   = row & (SS - 1);
    const int limit = ((q >> 7) + 1) << 7;
    const float* p = S + (long long)row * SS;
    bf16* ph = Ph + (long long)row * SS;
    bf16* pl = Pl + (long long)row * SS;

    const int tid = threadIdx.x;
    float v[8];
    float mx = -INFINITY;
#pragma unroll
    for (int i = 0; i < 8; i++) {
        int idx = i * 256 + tid;
        v[i] = (idx <= q) ? p[idx] : -INFINITY;
        mx = fmaxf(mx, v[i]);
    }

    __shared__ float red[256];
    red[tid] = mx;
    __syncthreads();
#pragma unroll
    for (int s = 128; s > 0; s >>= 1) {
        if (tid < s) red[tid] = fmaxf(red[tid], red[tid + s]);
        __syncthreads();
    }
    mx = red[0];
    __syncthreads();

    float e[8];
    float sum = 0.0f;
#pragma unroll
    for (int i = 0; i < 8; i++) {
        e[i] = __expf(v[i] - mx);
        sum += e[i];
    }
    red[tid] = sum;
    __syncthreads();
#pragma unroll
    for (int s = 128; s > 0; s >>= 1) {
        if (tid < s) red[tid] += red[tid + s];
        __syncthreads();
    }
    const float inv = 1.0f / red[0];

    const bf16 z16 = __float2bfloat16_rn(0.0f);
#pragma unroll
    for (int i = 0; i < 8; i++) {
        int idx = i * 256 + tid;
        if (idx <= q) {
            bf16 h, l;
            split1(e[i] * inv, h, l);
            ph[idx] = h;
            pl[idx] = l;
        } else if (idx < limit) {
            ph[idx] = z16;
            pl[idx] = z16;
        }
    }
}

// ---------------------------------------------------------------------------
// Launch sequence (graph-capturable: kernel launches only)
// ---------------------------------------------------------------------------
extern "C" void kernel_launch(void* const* d_in, const int* in_sizes, int n_in,
                              void* d_out, int out_size)
{
    const float* x  = (const float*)d_in[0];
    const float* Wq = (const float*)d_in[1];
    const float* Wk = (const float*)d_in[2];
    const float* Wv = (const float*)d_in[3];
    float* out = (float*)d_out;

    bf16 *Xh, *Xl, *Wth, *Wtl, *Qh, *Ql, *Kh, *Kl, *Vth, *Vtl, *Ph, *Pl;
    float *V, *Sb;
    cudaGetSymbolAddress((void**)&Xh,  g_Xh);
    cudaGetSymbolAddress((void**)&Xl,  g_Xl);
    cudaGetSymbolAddress((void**)&Wth, g_Wth);
    cudaGetSymbolAddress((void**)&Wtl, g_Wtl);
    cudaGetSymbolAddress((void**)&Qh,  g_Qh);
    cudaGetSymbolAddress((void**)&Ql,  g_Ql);
    cudaGetSymbolAddress((void**)&Kh,  g_Kh);
    cudaGetSymbolAddress((void**)&Kl,  g_Kl);
    cudaGetSymbolAddress((void**)&V,   g_V);
    cudaGetSymbolAddress((void**)&Vth, g_Vth);
    cudaGetSymbolAddress((void**)&Vtl, g_Vtl);
    cudaGetSymbolAddress((void**)&Sb,  g_S);
    cudaGetSymbolAddress((void**)&Ph,  g_Ph);
    cudaGetSymbolAddress((void**)&Pl,  g_Pl);

    const size_t wsz = (size_t)DD * DD;
    bf16 *WthQ = Wth, *WthK = Wth + wsz, *WthV = Wth + 2 * wsz;
    bf16 *WtlQ = Wtl, *WtlK = Wtl + wsz, *WtlV = Wtl + 2 * wsz;

    cudaFuncSetAttribute(mma_gemm<false, false, true>,
                         cudaFuncAttributeMaxDynamicSharedMemorySize, DSM_BYTES);
    cudaFuncSetAttribute(mma_gemm<false, false, false>,
                         cudaFuncAttributeMaxDynamicSharedMemorySize, DSM_BYTES);
    cudaFuncSetAttribute(mma_gemm<true, false, false>,
                         cudaFuncAttributeMaxDynamicSharedMemorySize, DSM_BYTES);
    cudaFuncSetAttribute(mma_gemm<false, true, false>,
                         cudaFuncAttributeMaxDynamicSharedMemorySize, DSM_BYTES);

    const long long sQKV = (long long)SS * DD;
    const long long sSco = (long long)SS * SS;
    const float scale = 0.03125f;     // 1024^-0.5

    dim3 tb(32, 8);

    // 0) split inputs: x and W^T
    const int xn4 = BB * SS * DD / 4;
    convert_split<<<(xn4 + 255) / 256, 256>>>(x, Xh, Xl, xn4);
    transpose_split<<<dim3(DD / 32, DD / 32, 1), tb>>>(Wq, WthQ, WtlQ, DD, DD, 0, 0);
    transpose_split<<<dim3(DD / 32, DD / 32, 1), tb>>>(Wk, WthK, WtlK, DD, DD, 0, 0);
    transpose_split<<<dim3(DD / 32, DD / 32, 1), tb>>>(Wv, WthV, WtlV, DD, DD, 0, 0);

    // 1) QKV projections (Q,K: split-bf16 epilogue; V: fp32 for transpose)
    dim3 gq(DD / TN, (BB * SS) / TM, 1);
    mma_gemm<false, false, true><<<gq, NTHREADS, DSM_BYTES>>>(
        Xh, Xl, DD, 0, WthQ, WtlQ, DD, 0, nullptr, Qh, Ql, DD, 0, DD, 1.0f);
    mma_gemm<false, false, true><<<gq, NTHREADS, DSM_BYTES>>>(
        Xh, Xl, DD, 0, WthK, WtlK, DD, 0, nullptr, Kh, Kl, DD, 0, DD, 1.0f);
    mma_gemm<false, false, false><<<gq, NTHREADS, DSM_BYTES>>>(
        Xh, Xl, DD, 0, WthV, WtlV, DD, 0, V, nullptr, nullptr, DD, 0, DD, 1.0f);

    // 2) V^T split per batch: [2048,1024] -> [1024,2048]
    transpose_split<<<dim3(DD / 32, SS / 32, BB), tb>>>(V, Vth, Vtl, SS, DD,
                                                        sQKV, sQKV);

    // 3) scores = scale * Q @ K^T (lower tiles only)
    dim3 gs(SS / TN, SS / TM, BB);
    mma_gemm<true, false, false><<<gs, NTHREADS, DSM_BYTES>>>(
        Qh, Ql, DD, sQKV, Kh, Kl, DD, sQKV, Sb, nullptr, nullptr, SS, sSco,
        DD, scale);

    // 4) causal softmax -> split-bf16 probs (+ zero-fill to 128 boundary)
    softmax_causal<<<BB * SS, 256>>>(Sb, Ph, Pl);

    // 5) out = P @ V  (per-q-tile K range)
    dim3 gp(DD / TN, SS / TM, BB);
    mma_gemm<false, true, false><<<gp, NTHREADS, DSM_BYTES>>>(
        Ph, Pl, SS, sSco, Vth, Vtl, SS, sQKV, out, nullptr, nullptr, DD, sQKV,
        0, 1.0f);
}

// round 5
// speedup vs baseline: 2.7252x; 1.0575x over previous
#include <cuda_runtime.h>
#include <cuda_bf16.h>
#include <cstdint>
#include <math.h>

#define BB 4
#define SS 2048
#define DD 1024

#define TM 128
#define TN 128
#define TK 32
#define NTHREADS 256
#define STAGES 3
#define STAGE_BYTES 32768
#define DSM_BYTES (STAGES * STAGE_BYTES + 1024)

typedef __nv_bfloat16 bf16;

// ---------------------------------------------------------------------------
// Scratch (__device__ globals: allocation-guard-safe)
// ---------------------------------------------------------------------------
__device__ bf16  g_Xh [(size_t)BB * SS * DD];
__device__ bf16  g_Xl [(size_t)BB * SS * DD];
__device__ bf16  g_Wth[3][(size_t)DD * DD];
__device__ bf16  g_Wtl[3][(size_t)DD * DD];
__device__ bf16  g_Qh [(size_t)BB * SS * DD];
__device__ bf16  g_Ql [(size_t)BB * SS * DD];
__device__ bf16  g_Kh [(size_t)BB * SS * DD];
__device__ bf16  g_Kl [(size_t)BB * SS * DD];
__device__ float g_V  [(size_t)BB * SS * DD];
__device__ bf16  g_Vth[(size_t)BB * SS * DD];
__device__ bf16  g_Vtl[(size_t)BB * SS * DD];
__device__ float g_S  [(size_t)BB * SS * SS];
__device__ bf16  g_Ph [(size_t)BB * SS * SS];
__device__ bf16  g_Pl [(size_t)BB * SS * SS];

// ---------------------------------------------------------------------------
// Helpers
// ---------------------------------------------------------------------------
__device__ __forceinline__ uint32_t smem_u32(const void* p) {
    uint32_t a;
    asm("{ .reg .u64 t; cvta.to.shared.u64 t, %1; cvt.u32.u64 %0, t; }"
        : "=r"(a) : "l"(p));
    return a;
}

// swizzle for 64-byte rows: XOR 16B-unit bits [5:4] with row bits [2:1]
#define SWZ(o) ((uint32_t)(o) ^ ((((uint32_t)(o)) >> 3) & 0x30u))

#define LDSM4(r, a)                                                        \
    asm volatile("ldmatrix.sync.aligned.m8n8.x4.shared.b16 "               \
                 "{%0,%1,%2,%3}, [%4];"                                    \
                 : "=r"((r)[0]), "=r"((r)[1]), "=r"((r)[2]), "=r"((r)[3])  \
                 : "r"(a))

#define MMA16816(d, a, b0, b1)                                             \
    asm volatile("mma.sync.aligned.m16n8k16.row.col.f32.bf16.bf16.f32 "    \
                 "{%0,%1,%2,%3},{%4,%5,%6,%7},{%8,%9},{%0,%1,%2,%3};"      \
                 : "+f"((d)[0]), "+f"((d)[1]), "+f"((d)[2]), "+f"((d)[3])  \
                 : "r"((a)[0]), "r"((a)[1]), "r"((a)[2]), "r"((a)[3]),     \
                   "r"(b0), "r"(b1))

#define CPA16(dst, src)                                                    \
    asm volatile("cp.async.cg.shared.global [%0], [%1], 16;"               \
                 :: "r"(dst), "l"(src))
#define CPA_COMMIT()  asm volatile("cp.async.commit_group;" ::: "memory")
#define CPA_WAIT1()   asm volatile("cp.async.wait_group 1;" ::: "memory")

__device__ __forceinline__ uint32_t pack2(bf16 a, bf16 b) {
    uint16_t ua = *reinterpret_cast<uint16_t*>(&a);
    uint16_t ub = *reinterpret_cast<uint16_t*>(&b);
    return (uint32_t)ua | ((uint32_t)ub << 16);
}

__device__ __forceinline__ void split1(float v, bf16& h, bf16& l) {
    h = __float2bfloat16_rn(v);
    l = __float2bfloat16_rn(v - __bfloat162float(h));
}

// ---------------------------------------------------------------------------
// Split-bf16 mma.sync GEMM, 3-stage cp.async, 256 thr, 2 CTAs/SM.
//   C[m,n] = alpha * sum_k A[m,k] * B[n,k]   (operands K-major bf16 hi/lo)
//   Warp tile 32x64 (warp grid 4m x 2n). Pass-major MMA order (hh, lh, hl)
//   with B-lo fragments reusing B-hi registers.
// Stage layout: Ah(8K) Al(8K) Bh(8K) Bl(8K) = 32KB; 3 stages = 96KB
// ---------------------------------------------------------------------------
template<bool TRI, bool PERQ, bool SPLIT_OUT>
__global__ void __launch_bounds__(NTHREADS, 2)
mma_gemm(const bf16* __restrict__ Ah, const bf16* __restrict__ Al,
         int lda, long long sA,
         const bf16* __restrict__ Bh, const bf16* __restrict__ Bl,
         int ldb, long long sB,
         float* __restrict__ Cf, bf16* __restrict__ Ch, bf16* __restrict__ Cl,
         int ldc, long long sC, int Kfull, float alpha)
{
    if (TRI && blockIdx.x > blockIdx.y) return;

    extern __shared__ char dsm[];
    const uint32_t sbase = (smem_u32(dsm) + 1023u) & ~1023u;

    const long long z = blockIdx.z;
    Ah += sA * z; Al += sA * z; Bh += sB * z; Bl += sB * z;

    const int m0 = blockIdx.y * TM;
    const int n0 = blockIdx.x * TN;
    const int Klim = PERQ ? (int)(blockIdx.y + 1) * TM : Kfull;
    const int KB = Klim / TK;

    const int tid  = threadIdx.x;
    const int lane = tid & 31;
    const int wid  = tid >> 5;
    const int wm = (wid & 3) * 32;        // warp m offset
    const int wn = (wid >> 2) * 64;       // warp n offset

    // cp.async: per array 128 rows x 4 16B-chunks = 512 tasks, 2 per thread
    const int r0g = tid >> 2, c4 = tid & 3;          // task 0: row r0g
    const uint32_t st0 = SWZ(r0g * 64 + c4 * 16);    // task 1: row r0g+64
    const uint32_t st1 = SWZ((r0g + 64) * 64 + c4 * 16);
    const bf16* gAh = Ah + (long long)(m0 + r0g) * lda + c4 * 8;
    const bf16* gAl = Al + (long long)(m0 + r0g) * lda + c4 * 8;
    const bf16* gBh = Bh + (long long)(n0 + r0g) * ldb + c4 * 8;
    const bf16* gBl = Bl + (long long)(n0 + r0g) * ldb + c4 * 8;
    const long long rowskip = (long long)64 * lda;   // lda==ldb for all uses? no!
    const long long rowskipB = (long long)64 * ldb;

    // ldmatrix lane offsets
    uint32_t aOff[2], bOff[4];
    {
        const int r  = lane & 15;
        const int hb = (lane >> 4) * 16;
        aOff[0] = SWZ((wm +      r) * 64 + hb);
        aOff[1] = SWZ((wm + 16 + r) * 64 + hb);
#pragma unroll
        for (int g = 0; g < 4; g++)
            bOff[g] = SWZ((wn + 16 * g + r) * 64 + hb);
    }

    float acc[2][8][4];
#pragma unroll
    for (int mf = 0; mf < 2; mf++)
#pragma unroll
        for (int nf = 0; nf < 8; nf++)
#pragma unroll
            for (int j = 0; j < 4; j++) acc[mf][nf][j] = 0.0f;

#define ISSUE_STAGE(sidx, k0)                                              \
    do {                                                                   \
        const uint32_t sb_ = sbase + (uint32_t)(sidx) * STAGE_BYTES;       \
        CPA16(sb_ +          st0, gAh + (k0));                             \
        CPA16(sb_ +          st1, gAh + (k0) + rowskip);                   \
        CPA16(sb_ +  8192u + st0, gAl + (k0));                             \
        CPA16(sb_ +  8192u + st1, gAl + (k0) + rowskip);                   \
        CPA16(sb_ + 16384u + st0, gBh + (k0));                             \
        CPA16(sb_ + 16384u + st1, gBh + (k0) + rowskipB);                  \
        CPA16(sb_ + 24576u + st0, gBl + (k0));                             \
        CPA16(sb_ + 24576u + st1, gBl + (k0) + rowskipB);                  \
    } while (0)

    // ---- prologue: stages 0..1 ----
#pragma unroll
    for (int s = 0; s < STAGES - 1; s++) {
        if (s < KB) ISSUE_STAGE(s, s * TK);
        CPA_COMMIT();
    }

    int sidx_c = 0;                  // stage index being computed
    int sidx_w = STAGES - 1;         // stage index to write next
    for (int kb = 0; kb < KB; kb++) {
        CPA_WAIT1();
        __syncthreads();

        if (kb + STAGES - 1 < KB)
            ISSUE_STAGE(sidx_w, (kb + STAGES - 1) * TK);
        CPA_COMMIT();
        if (++sidx_w == STAGES) sidx_w = 0;

        const uint32_t buf = sbase + (uint32_t)sidx_c * STAGE_BYTES;
        if (++sidx_c == STAGES) sidx_c = 0;

#pragma unroll
        for (int c = 0; c < 2; c++) {
            const uint32_t ko = (uint32_t)(c * 32);
            uint32_t ah[2][4], al[2][4], bb[4][4];
            LDSM4(ah[0], buf +          (aOff[0] ^ ko));
            LDSM4(ah[1], buf +          (aOff[1] ^ ko));
            LDSM4(al[0], buf +  8192u + (aOff[0] ^ ko));
            LDSM4(al[1], buf +  8192u + (aOff[1] ^ ko));
#pragma unroll
            for (int g = 0; g < 4; g++)
                LDSM4(bb[g], buf + 16384u + (bOff[g] ^ ko));

            // pass 1: ah * bh
#pragma unroll
            for (int mf = 0; mf < 2; mf++)
#pragma unroll
                for (int nf = 0; nf < 8; nf++) {
                    const int g = nf >> 1, s = nf & 1;
                    MMA16816(acc[mf][nf], ah[mf], bb[g][s], bb[g][s + 2]);
                }
            // pass 2: al * bh
#pragma unroll
            for (int mf = 0; mf < 2; mf++)
#pragma unroll
                for (int nf = 0; nf < 8; nf++) {
                    const int g = nf >> 1, s = nf & 1;
                    MMA16816(acc[mf][nf], al[mf], bb[g][s], bb[g][s + 2]);
                }
            // bh dead -> overwrite with bl
#pragma unroll
            for (int g = 0; g < 4; g++)
                LDSM4(bb[g], buf + 24576u + (bOff[g] ^ ko));
            // pass 3: ah * bl
#pragma unroll
            for (int mf = 0; mf < 2; mf++)
#pragma unroll
                for (int nf = 0; nf < 8; nf++) {
                    const int g = nf >> 1, s = nf & 1;
                    MMA16816(acc[mf][nf], ah[mf], bb[g][s], bb[g][s + 2]);
                }
        }
    }
#undef ISSUE_STAGE

    // ---- epilogue ----
    const int g = lane >> 2, t = lane & 3;
    Cf += sC * z; Ch += sC * z; Cl += sC * z;
#pragma unroll
    for (int mf = 0; mf < 2; mf++) {
#pragma unroll
        for (int nf = 0; nf < 8; nf++) {
            const int r0  = m0 + wm + 16 * mf + g;
            const int col = n0 + wn + 8 * nf + 2 * t;
            float v0 = acc[mf][nf][0] * alpha;
            float v1 = acc[mf][nf][1] * alpha;
            float v2 = acc[mf][nf][2] * alpha;
            float v3 = acc[mf][nf][3] * alpha;
            if (SPLIT_OUT) {
                bf16 h0, l0, h1, l1, h2, l2, h3, l3;
                split1(v0, h0, l0); split1(v1, h1, l1);
                split1(v2, h2, l2); split1(v3, h3, l3);
                *reinterpret_cast<uint32_t*>(Ch + (long long)r0 * ldc + col)       = pack2(h0, h1);
                *reinterpret_cast<uint32_t*>(Cl + (long long)r0 * ldc + col)       = pack2(l0, l1);
                *reinterpret_cast<uint32_t*>(Ch + (long long)(r0 + 8) * ldc + col) = pack2(h2, h3);
                *reinterpret_cast<uint32_t*>(Cl + (long long)(r0 + 8) * ldc + col) = pack2(l2, l3);
            } else {
                float2 a0, a1;
                a0.x = v0; a0.y = v1; a1.x = v2; a1.y = v3;
                *reinterpret_cast<float2*>(Cf + (long long)r0 * ldc + col)       = a0;
                *reinterpret_cast<float2*>(Cf + (long long)(r0 + 8) * ldc + col) = a1;
            }
        }
    }
}

// ---------------------------------------------------------------------------
// fp32 -> split bf16 hi/lo elementwise (vectorized x4)
// ---------------------------------------------------------------------------
__global__ void __launch_bounds__(256)
convert_split(const float* __restrict__ in, bf16* __restrict__ oh,
              bf16* __restrict__ ol, int n4)
{
    int i = blockIdx.x * 256 + threadIdx.x;
    if (i >= n4) return;
    float4 v = reinterpret_cast<const float4*>(in)[i];
    bf16 h0, l0, h1, l1, h2, l2, h3, l3;
    split1(v.x, h0, l0); split1(v.y, h1, l1);
    split1(v.z, h2, l2); split1(v.w, h3, l3);
    reinterpret_cast<uint32_t*>(oh)[2 * i]     = pack2(h0, h1);
    reinterpret_cast<uint32_t*>(oh)[2 * i + 1] = pack2(h2, h3);
    reinterpret_cast<uint32_t*>(ol)[2 * i]     = pack2(l0, l1);
    reinterpret_cast<uint32_t*>(ol)[2 * i + 1] = pack2(l2, l3);
}

// ---------------------------------------------------------------------------
// fp32 [R x C] -> transposed split bf16 hi/lo [C x R] (per-z batch)
// ---------------------------------------------------------------------------
__global__ void __launch_bounds__(256)
transpose_split(const float* __restrict__ in, bf16* __restrict__ oh,
                bf16* __restrict__ ol, int R, int C,
                long long sIn, long long sOut)
{
    __shared__ float t[32][33];
    in += sIn * blockIdx.z;
    oh += sOut * blockIdx.z;
    ol += sOut * blockIdx.z;
    const int c0 = blockIdx.x * 32, r0 = blockIdx.y * 32;
#pragma unroll
    for (int j = threadIdx.y; j < 32; j += 8)
        t[j][threadIdx.x] = in[(long long)(r0 + j) * C + c0 + threadIdx.x];
    __syncthreads();
#pragma unroll
    for (int j = threadIdx.y; j < 32; j += 8) {
        float v = t[threadIdx.x][j];
        bf16 h, l;
        split1(v, h, l);
        oh[(long long)(c0 + j) * R + r0 + threadIdx.x] = h;
        ol[(long long)(c0 + j) * R + r0 + threadIdx.x] = l;
    }
}

// ---------------------------------------------------------------------------
// Causal row softmax: fp32 scores -> split-bf16 probs; zero-fill to the
// 128-aligned block end so P@V needs no masking.
// ---------------------------------------------------------------------------
__global__ void __launch_bounds__(256)
softmax_causal(const float* __restrict__ S, bf16* __restrict__ Ph,
               bf16* __restrict__ Pl)
{
    const int row = blockIdx.x;          // b*S + q
    const int q   = row & (SS - 1);
    const int limit = ((q >> 7) + 1) << 7;
    const float* p = S + (long long)row * SS;
    bf16* ph = Ph + (long long)row * SS;
    bf16* pl = Pl + (long long)row * SS;

    const int tid = threadIdx.x;
    float v[8];
    float mx = -INFINITY;
#pragma unroll
    for (int i = 0; i < 8; i++) {
        int idx = i * 256 + tid;
        v[i] = (idx <= q) ? p[idx] : -INFINITY;
        mx = fmaxf(mx, v[i]);
    }

    __shared__ float red[256];
    red[tid] = mx;
    __syncthreads();
#pragma unroll
    for (int s = 128; s > 0; s >>= 1) {
        if (tid < s) red[tid] = fmaxf(red[tid], red[tid + s]);
        __syncthreads();
    }
    mx = red[0];
    __syncthreads();

    float e[8];
    float sum = 0.0f;
#pragma unroll
    for (int i = 0; i < 8; i++) {
        e[i] = __expf(v[i] - mx);
        sum += e[i];
    }
    red[tid] = sum;
    __syncthreads();
#pragma unroll
    for (int s = 128; s > 0; s >>= 1) {
        if (tid < s) red[tid] += red[tid + s];
        __syncthreads();
    }
    const float inv = 1.0f / red[0];

    const bf16 z16 = __float2bfloat16_rn(0.0f);
#pragma unroll
    for (int i = 0; i < 8; i++) {
        int idx = i * 256 + tid;
        if (idx <= q) {
            bf16 h, l;
            split1(e[i] * inv, h, l);
            ph[idx] = h;
            pl[idx] = l;
        } else if (idx < limit) {
            ph[idx] = z16;
            pl[idx] = z16;
        }
    }
}

// ---------------------------------------------------------------------------
// Launch sequence (graph-capturable: kernel launches only)
// ---------------------------------------------------------------------------
extern "C" void kernel_launch(void* const* d_in, const int* in_sizes, int n_in,
                              void* d_out, int out_size)
{
    const float* x  = (const float*)d_in[0];
    const float* Wq = (const float*)d_in[1];
    const float* Wk = (const float*)d_in[2];
    const float* Wv = (const float*)d_in[3];
    float* out = (float*)d_out;

    bf16 *Xh, *Xl, *Wth, *Wtl, *Qh, *Ql, *Kh, *Kl, *Vth, *Vtl, *Ph, *Pl;
    float *V, *Sb;
    cudaGetSymbolAddress((void**)&Xh,  g_Xh);
    cudaGetSymbolAddress((void**)&Xl,  g_Xl);
    cudaGetSymbolAddress((void**)&Wth, g_Wth);
    cudaGetSymbolAddress((void**)&Wtl, g_Wtl);
    cudaGetSymbolAddress((void**)&Qh,  g_Qh);
    cudaGetSymbolAddress((void**)&Ql,  g_Ql);
    cudaGetSymbolAddress((void**)&Kh,  g_Kh);
    cudaGetSymbolAddress((void**)&Kl,  g_Kl);
    cudaGetSymbolAddress((void**)&V,   g_V);
    cudaGetSymbolAddress((void**)&Vth, g_Vth);
    cudaGetSymbolAddress((void**)&Vtl, g_Vtl);
    cudaGetSymbolAddress((void**)&Sb,  g_S);
    cudaGetSymbolAddress((void**)&Ph,  g_Ph);
    cudaGetSymbolAddress((void**)&Pl,  g_Pl);

    const size_t wsz = (size_t)DD * DD;
    bf16 *WthQ = Wth, *WthK = Wth + wsz, *WthV = Wth + 2 * wsz;
    bf16 *WtlQ = Wtl, *WtlK = Wtl + wsz, *WtlV = Wtl + 2 * wsz;

    cudaFuncSetAttribute(mma_gemm<false, false, true>,
                         cudaFuncAttributeMaxDynamicSharedMemorySize, DSM_BYTES);
    cudaFuncSetAttribute(mma_gemm<false, false, false>,
                         cudaFuncAttributeMaxDynamicSharedMemorySize, DSM_BYTES);
    cudaFuncSetAttribute(mma_gemm<true, false, false>,
                         cudaFuncAttributeMaxDynamicSharedMemorySize, DSM_BYTES);
    cudaFuncSetAttribute(mma_gemm<false, true, false>,
                         cudaFuncAttributeMaxDynamicSharedMemorySize, DSM_BYTES);

    const long long sQKV = (long long)SS * DD;
    const long long sSco = (long long)SS * SS;
    const float scale = 0.03125f;     // 1024^-0.5

    dim3 tb(32, 8);

    // 0) split inputs: x and W^T
    const int xn4 = BB * SS * DD / 4;
    convert_split<<<(xn4 + 255) / 256, 256>>>(x, Xh, Xl, xn4);
    transpose_split<<<dim3(DD / 32, DD / 32, 1), tb>>>(Wq, WthQ, WtlQ, DD, DD, 0, 0);
    transpose_split<<<dim3(DD / 32, DD / 32, 1), tb>>>(Wk, WthK, WtlK, DD, DD, 0, 0);
    transpose_split<<<dim3(DD / 32, DD / 32, 1), tb>>>(Wv, WthV, WtlV, DD, DD, 0, 0);

    // 1) QKV projections (Q,K: split-bf16 epilogue; V: fp32 for transpose)
    dim3 gq(DD / TN, (BB * SS) / TM, 1);
    mma_gemm<false, false, true><<<gq, NTHREADS, DSM_BYTES>>>(
        Xh, Xl, DD, 0, WthQ, WtlQ, DD, 0, nullptr, Qh, Ql, DD, 0, DD, 1.0f);
    mma_gemm<false, false, true><<<gq, NTHREADS, DSM_BYTES>>>(
        Xh, Xl, DD, 0, WthK, WtlK, DD, 0, nullptr, Kh, Kl, DD, 0, DD, 1.0f);
    mma_gemm<false, false, false><<<gq, NTHREADS, DSM_BYTES>>>(
        Xh, Xl, DD, 0, WthV, WtlV, DD, 0, V, nullptr, nullptr, DD, 0, DD, 1.0f);

    // 2) V^T split per batch: [2048,1024] -> [1024,2048]
    transpose_split<<<dim3(DD / 32, SS / 32, BB), tb>>>(V, Vth, Vtl, SS, DD,
                                                        sQKV, sQKV);

    // 3) scores = scale * Q @ K^T (lower tiles only)
    dim3 gs(SS / TN, SS / TM, BB);
    mma_gemm<true, false, false><<<gs, NTHREADS, DSM_BYTES>>>(
        Qh, Ql, DD, sQKV, Kh, Kl, DD, sQKV, Sb, nullptr, nullptr, SS, sSco,
        DD, scale);

    // 4) causal softmax -> split-bf16 probs (+ zero-fill to 128 boundary)
    softmax_causal<<<BB * SS, 256>>>(Sb, Ph, Pl);

    // 5) out = P @ V  (per-q-tile K range)
    dim3 gp(DD / TN, SS / TM, BB);
    mma_gemm<false, true, false><<<gp, NTHREADS, DSM_BYTES>>>(
        Ph, Pl, SS, sSco, Vth, Vtl, SS, sQKV, out, nullptr, nullptr, DD, sQKV,
        0, 1.0f);
}

// round 6
// speedup vs baseline: 2.8888x; 1.0600x over previous
#include <cuda_runtime.h>
#include <cuda_bf16.h>
#include <cstdint>
#include <math.h>

#define BB 4
#define SS 2048
#define DD 1024

#define TM 128
#define TN 64
#define TK 32
#define NTHREADS 256
#define STAGES 3
#define STAGE_BYTES 24576            // Ah 8K | Al 8K | Bh 4K | Bl 4K
#define DSM_BYTES (STAGES * STAGE_BYTES + 1024)

typedef __nv_bfloat16 bf16;

// ---------------------------------------------------------------------------
// Scratch (__device__ globals: allocation-guard-safe)
// ---------------------------------------------------------------------------
__device__ bf16  g_Xh [(size_t)BB * SS * DD];
__device__ bf16  g_Xl [(size_t)BB * SS * DD];
__device__ bf16  g_Wth[3][(size_t)DD * DD];
__device__ bf16  g_Wtl[3][(size_t)DD * DD];
__device__ bf16  g_Qh [(size_t)BB * SS * DD];
__device__ bf16  g_Ql [(size_t)BB * SS * DD];
__device__ bf16  g_Kh [(size_t)BB * SS * DD];
__device__ bf16  g_Kl [(size_t)BB * SS * DD];
__device__ float g_V  [(size_t)BB * SS * DD];
__device__ bf16  g_Vth[(size_t)BB * SS * DD];
__device__ bf16  g_Vtl[(size_t)BB * SS * DD];
__device__ float g_S  [(size_t)BB * SS * SS];
__device__ bf16  g_Ph [(size_t)BB * SS * SS];
__device__ bf16  g_Pl [(size_t)BB * SS * SS];

// ---------------------------------------------------------------------------
// Helpers
// ---------------------------------------------------------------------------
__device__ __forceinline__ uint32_t smem_u32(const void* p) {
    uint32_t a;
    asm("{ .reg .u64 t; cvta.to.shared.u64 t, %1; cvt.u32.u64 %0, t; }"
        : "=r"(a) : "l"(p));
    return a;
}

// swizzle for 64-byte rows: XOR 16B-unit bits [5:4] with row bits [2:1]
#define SWZ(o) ((uint32_t)(o) ^ ((((uint32_t)(o)) >> 3) & 0x30u))

#define LDSM4(r, a)                                                        \
    asm volatile("ldmatrix.sync.aligned.m8n8.x4.shared.b16 "               \
                 "{%0,%1,%2,%3}, [%4];"                                    \
                 : "=r"((r)[0]), "=r"((r)[1]), "=r"((r)[2]), "=r"((r)[3])  \
                 : "r"(a))

#define MMA16816(d, a, b0, b1)                                             \
    asm volatile("mma.sync.aligned.m16n8k16.row.col.f32.bf16.bf16.f32 "    \
                 "{%0,%1,%2,%3},{%4,%5,%6,%7},{%8,%9},{%0,%1,%2,%3};"      \
                 : "+f"((d)[0]), "+f"((d)[1]), "+f"((d)[2]), "+f"((d)[3])  \
                 : "r"((a)[0]), "r"((a)[1]), "r"((a)[2]), "r"((a)[3]),     \
                   "r"(b0), "r"(b1))

#define CPA16(dst, src)                                                    \
    asm volatile("cp.async.cg.shared.global [%0], [%1], 16;"               \
                 :: "r"(dst), "l"(src))
#define CPA_COMMIT()  asm volatile("cp.async.commit_group;" ::: "memory")
#define CPA_WAIT1()   asm volatile("cp.async.wait_group 1;" ::: "memory")

__device__ __forceinline__ uint32_t pack2(bf16 a, bf16 b) {
    uint16_t ua = *reinterpret_cast<uint16_t*>(&a);
    uint16_t ub = *reinterpret_cast<uint16_t*>(&b);
    return (uint32_t)ua | ((uint32_t)ub << 16);
}

__device__ __forceinline__ void split1(float v, bf16& h, bf16& l) {
    h = __float2bfloat16_rn(v);
    l = __float2bfloat16_rn(v - __bfloat162float(h));
}

// ---------------------------------------------------------------------------
// Split-bf16 mma.sync GEMM, CTA tile 128x64, 3-stage cp.async, 3 CTAs/SM.
//   C[m,n] = alpha * sum_k A[m,k] * B[n,k]   (operands K-major bf16 hi/lo)
//   Warp grid 4m x 2n, warp tile 32x32. Pass-major order (hh, lh, hl),
//   B-lo reuses B-hi registers.
//   TRI : skip tiles fully above the diagonal (n0 > m0+TM-1)
//   PERQ: K limit = (by+1)*TM
// ---------------------------------------------------------------------------
template<bool TRI, bool PERQ, bool SPLIT_OUT>
__global__ void __launch_bounds__(NTHREADS, 3)
mma_gemm(const bf16* __restrict__ Ah, const bf16* __restrict__ Al,
         int lda, long long sA,
         const bf16* __restrict__ Bh, const bf16* __restrict__ Bl,
         int ldb, long long sB,
         float* __restrict__ Cf, bf16* __restrict__ Ch, bf16* __restrict__ Cl,
         int ldc, long long sC, int Kfull, float alpha)
{
    const int m0 = blockIdx.y * TM;
    const int n0 = blockIdx.x * TN;
    if (TRI && n0 > m0 + TM - 1) return;

    extern __shared__ char dsm[];
    const uint32_t sbase = (smem_u32(dsm) + 1023u) & ~1023u;

    const long long z = blockIdx.z;
    Ah += sA * z; Al += sA * z; Bh += sB * z; Bl += sB * z;

    const int Klim = PERQ ? (int)(blockIdx.y + 1) * TM : Kfull;
    const int KB = Klim / TK;

    const int tid  = threadIdx.x;
    const int lane = tid & 31;
    const int wid  = tid >> 5;
    const int wm = (wid & 3) * 32;        // warp m offset
    const int wn = (wid >> 2) * 32;       // warp n offset

    // cp.async: A = 128 rows x 4 16B-chunks (2 tasks/thr), B = 64 rows (1 task)
    const int r0g = tid >> 2, c4 = tid & 3;
    const uint32_t st0 = SWZ(r0g * 64 + c4 * 16);
    const uint32_t st1 = SWZ((r0g + 64) * 64 + c4 * 16);
    const bf16* gAh = Ah + (long long)(m0 + r0g) * lda + c4 * 8;
    const bf16* gAl = Al + (long long)(m0 + r0g) * lda + c4 * 8;
    const bf16* gBh = Bh + (long long)(n0 + r0g) * ldb + c4 * 8;   // r0g < 64
    const bf16* gBl = Bl + (long long)(n0 + r0g) * ldb + c4 * 8;
    const long long rowskip = (long long)64 * lda;

    // ldmatrix lane offsets
    uint32_t aOff[2], bOff[2];
    {
        const int r  = lane & 15;
        const int hb = (lane >> 4) * 16;
        aOff[0] = SWZ((wm +      r) * 64 + hb);
        aOff[1] = SWZ((wm + 16 + r) * 64 + hb);
        bOff[0] = SWZ((wn +      r) * 64 + hb);
        bOff[1] = SWZ((wn + 16 + r) * 64 + hb);
    }

    float acc[2][4][4];
#pragma unroll
    for (int mf = 0; mf < 2; mf++)
#pragma unroll
        for (int nf = 0; nf < 4; nf++)
#pragma unroll
            for (int j = 0; j < 4; j++) acc[mf][nf][j] = 0.0f;

#define ISSUE_STAGE(sidx, k0)                                              \
    do {                                                                   \
        const uint32_t sb_ = sbase + (uint32_t)(sidx) * STAGE_BYTES;       \
        CPA16(sb_ +          st0, gAh + (k0));                             \
        CPA16(sb_ +          st1, gAh + (k0) + rowskip);                   \
        CPA16(sb_ +  8192u + st0, gAl + (k0));                             \
        CPA16(sb_ +  8192u + st1, gAl + (k0) + rowskip);                   \
        CPA16(sb_ + 16384u + st0, gBh + (k0));                             \
        CPA16(sb_ + 20480u + st0, gBl + (k0));                             \
    } while (0)

    // ---- prologue: stages 0..1 ----
#pragma unroll
    for (int s = 0; s < STAGES - 1; s++) {
        if (s < KB) ISSUE_STAGE(s, s * TK);
        CPA_COMMIT();
    }

    int sidx_c = 0;
    int sidx_w = STAGES - 1;
    for (int kb = 0; kb < KB; kb++) {
        CPA_WAIT1();
        __syncthreads();

        if (kb + STAGES - 1 < KB)
            ISSUE_STAGE(sidx_w, (kb + STAGES - 1) * TK);
        CPA_COMMIT();
        if (++sidx_w == STAGES) sidx_w = 0;

        const uint32_t buf = sbase + (uint32_t)sidx_c * STAGE_BYTES;
        if (++sidx_c == STAGES) sidx_c = 0;

#pragma unroll
        for (int c = 0; c < 2; c++) {
            const uint32_t ko = (uint32_t)(c * 32);
            uint32_t ah[2][4], al[2][4], bb[2][4];
            LDSM4(ah[0], buf +          (aOff[0] ^ ko));
            LDSM4(ah[1], buf +          (aOff[1] ^ ko));
            LDSM4(al[0], buf +  8192u + (aOff[0] ^ ko));
            LDSM4(al[1], buf +  8192u + (aOff[1] ^ ko));
            LDSM4(bb[0], buf + 16384u + (bOff[0] ^ ko));
            LDSM4(bb[1], buf + 16384u + (bOff[1] ^ ko));

            // pass 1: ah * bh
#pragma unroll
            for (int mf = 0; mf < 2; mf++)
#pragma unroll
                for (int nf = 0; nf < 4; nf++) {
                    const int g = nf >> 1, s = nf & 1;
                    MMA16816(acc[mf][nf], ah[mf], bb[g][s], bb[g][s + 2]);
                }
            // pass 2: al * bh
#pragma unroll
            for (int mf = 0; mf < 2; mf++)
#pragma unroll
                for (int nf = 0; nf < 4; nf++) {
                    const int g = nf >> 1, s = nf & 1;
                    MMA16816(acc[mf][nf], al[mf], bb[g][s], bb[g][s + 2]);
                }
            // bh dead -> load bl into same regs
            LDSM4(bb[0], buf + 20480u + (bOff[0] ^ ko));
            LDSM4(bb[1], buf + 20480u + (bOff[1] ^ ko));
            // pass 3: ah * bl
#pragma unroll
            for (int mf = 0; mf < 2; mf++)
#pragma unroll
                for (int nf = 0; nf < 4; nf++) {
                    const int g = nf >> 1, s = nf & 1;
                    MMA16816(acc[mf][nf], ah[mf], bb[g][s], bb[g][s + 2]);
                }
        }
    }
#undef ISSUE_STAGE

    // ---- epilogue ----
    const int g = lane >> 2, t = lane & 3;
    Cf += sC * z; Ch += sC * z; Cl += sC * z;
#pragma unroll
    for (int mf = 0; mf < 2; mf++) {
#pragma unroll
        for (int nf = 0; nf < 4; nf++) {
            const int r0  = m0 + wm + 16 * mf + g;
            const int col = n0 + wn + 8 * nf + 2 * t;
            float v0 = acc[mf][nf][0] * alpha;
            float v1 = acc[mf][nf][1] * alpha;
            float v2 = acc[mf][nf][2] * alpha;
            float v3 = acc[mf][nf][3] * alpha;
            if (SPLIT_OUT) {
                bf16 h0, l0, h1, l1, h2, l2, h3, l3;
                split1(v0, h0, l0); split1(v1, h1, l1);
                split1(v2, h2, l2); split1(v3, h3, l3);
                *reinterpret_cast<uint32_t*>(Ch + (long long)r0 * ldc + col)       = pack2(h0, h1);
                *reinterpret_cast<uint32_t*>(Cl + (long long)r0 * ldc + col)       = pack2(l0, l1);
                *reinterpret_cast<uint32_t*>(Ch + (long long)(r0 + 8) * ldc + col) = pack2(h2, h3);
                *reinterpret_cast<uint32_t*>(Cl + (long long)(r0 + 8) * ldc + col) = pack2(l2, l3);
            } else {
                float2 a0, a1;
                a0.x = v0; a0.y = v1; a1.x = v2; a1.y = v3;
                *reinterpret_cast<float2*>(Cf + (long long)r0 * ldc + col)       = a0;
                *reinterpret_cast<float2*>(Cf + (long long)(r0 + 8) * ldc + col) = a1;
            }
        }
    }
}

// ---------------------------------------------------------------------------
// fp32 -> split bf16 hi/lo elementwise (vectorized x4)
// ---------------------------------------------------------------------------
__global__ void __launch_bounds__(256)
convert_split(const float* __restrict__ in, bf16* __restrict__ oh,
              bf16* __restrict__ ol, int n4)
{
    int i = blockIdx.x * 256 + threadIdx.x;
    if (i >= n4) return;
    float4 v = reinterpret_cast<const float4*>(in)[i];
    bf16 h0, l0, h1, l1, h2, l2, h3, l3;
    split1(v.x, h0, l0); split1(v.y, h1, l1);
    split1(v.z, h2, l2); split1(v.w, h3, l3);
    reinterpret_cast<uint32_t*>(oh)[2 * i]     = pack2(h0, h1);
    reinterpret_cast<uint32_t*>(oh)[2 * i + 1] = pack2(h2, h3);
    reinterpret_cast<uint32_t*>(ol)[2 * i]     = pack2(l0, l1);
    reinterpret_cast<uint32_t*>(ol)[2 * i + 1] = pack2(l2, l3);
}

// ---------------------------------------------------------------------------
// fp32 [R x C] -> transposed split bf16 hi/lo [C x R] (per-z batch)
// ---------------------------------------------------------------------------
__global__ void __launch_bounds__(256)
transpose_split(const float* __restrict__ in, bf16* __restrict__ oh,
                bf16* __restrict__ ol, int R, int C,
                long long sIn, long long sOut)
{
    __shared__ float t[32][33];
    in += sIn * blockIdx.z;
    oh += sOut * blockIdx.z;
    ol += sOut * blockIdx.z;
    const int c0 = blockIdx.x * 32, r0 = blockIdx.y * 32;
#pragma unroll
    for (int j = threadIdx.y; j < 32; j += 8)
        t[j][threadIdx.x] = in[(long long)(r0 + j) * C + c0 + threadIdx.x];
    __syncthreads();
#pragma unroll
    for (int j = threadIdx.y; j < 32; j += 8) {
        float v = t[threadIdx.x][j];
        bf16 h, l;
        split1(v, h, l);
        oh[(long long)(c0 + j) * R + r0 + threadIdx.x] = h;
        ol[(long long)(c0 + j) * R + r0 + threadIdx.x] = l;
    }
}

// ---------------------------------------------------------------------------
// Causal row softmax: fp32 scores -> split-bf16 probs; zero-fill to the
// 128-aligned block end so P@V needs no masking.
// ---------------------------------------------------------------------------
__global__ void __launch_bounds__(256)
softmax_causal(const float* __restrict__ S, bf16* __restrict__ Ph,
               bf16* __restrict__ Pl)
{
    const int row = blockIdx.x;          // b*S + q
    const int q   = row & (SS - 1);
    const int limit = ((q >> 7) + 1) << 7;
    const float* p = S + (long long)row * SS;
    bf16* ph = Ph + (long long)row * SS;
    bf16* pl = Pl + (long long)row * SS;

    const int tid = threadIdx.x;
    float v[8];
    float mx = -INFINITY;
#pragma unroll
    for (int i = 0; i < 8; i++) {
        int idx = i * 256 + tid;
        v[i] = (idx <= q) ? p[idx] : -INFINITY;
        mx = fmaxf(mx, v[i]);
    }

    __shared__ float red[256];
    red[tid] = mx;
    __syncthreads();
#pragma unroll
    for (int s = 128; s > 0; s >>= 1) {
        if (tid < s) red[tid] = fmaxf(red[tid], red[tid + s]);
        __syncthreads();
    }
    mx = red[0];
    __syncthreads();

    float e[8];
    float sum = 0.0f;
#pragma unroll
    for (int i = 0; i < 8; i++) {
        e[i] = __expf(v[i] - mx);
        sum += e[i];
    }
    red[tid] = sum;
    __syncthreads();
#pragma unroll
    for (int s = 128; s > 0; s >>= 1) {
        if (tid < s) red[tid] += red[tid + s];
        __syncthreads();
    }
    const float inv = 1.0f / red[0];

    const bf16 z16 = __float2bfloat16_rn(0.0f);
#pragma unroll
    for (int i = 0; i < 8; i++) {
        int idx = i * 256 + tid;
        if (idx <= q) {
            bf16 h, l;
            split1(e[i] * inv, h, l);
            ph[idx] = h;
            pl[idx] = l;
        } else if (idx < limit) {
            ph[idx] = z16;
            pl[idx] = z16;
        }
    }
}

// ---------------------------------------------------------------------------
// Launch sequence (graph-capturable: kernel launches only)
// ---------------------------------------------------------------------------
extern "C" void kernel_launch(void* const* d_in, const int* in_sizes, int n_in,
                              void* d_out, int out_size)
{
    const float* x  = (const float*)d_in[0];
    const float* Wq = (const float*)d_in[1];
    const float* Wk = (const float*)d_in[2];
    const float* Wv = (const float*)d_in[3];
    float* out = (float*)d_out;

    bf16 *Xh, *Xl, *Wth, *Wtl, *Qh, *Ql, *Kh, *Kl, *Vth, *Vtl, *Ph, *Pl;
    float *V, *Sb;
    cudaGetSymbolAddress((void**)&Xh,  g_Xh);
    cudaGetSymbolAddress((void**)&Xl,  g_Xl);
    cudaGetSymbolAddress((void**)&Wth, g_Wth);
    cudaGetSymbolAddress((void**)&Wtl, g_Wtl);
    cudaGetSymbolAddress((void**)&Qh,  g_Qh);
    cudaGetSymbolAddress((void**)&Ql,  g_Ql);
    cudaGetSymbolAddress((void**)&Kh,  g_Kh);
    cudaGetSymbolAddress((void**)&Kl,  g_Kl);
    cudaGetSymbolAddress((void**)&V,   g_V);
    cudaGetSymbolAddress((void**)&Vth, g_Vth);
    cudaGetSymbolAddress((void**)&Vtl, g_Vtl);
    cudaGetSymbolAddress((void**)&Sb,  g_S);
    cudaGetSymbolAddress((void**)&Ph,  g_Ph);
    cudaGetSymbolAddress((void**)&Pl,  g_Pl);

    const size_t wsz = (size_t)DD * DD;
    bf16 *WthQ = Wth, *WthK = Wth + wsz, *WthV = Wth + 2 * wsz;
    bf16 *WtlQ = Wtl, *WtlK = Wtl + wsz, *WtlV = Wtl + 2 * wsz;

    cudaFuncSetAttribute(mma_gemm<false, false, true>,
                         cudaFuncAttributeMaxDynamicSharedMemorySize, DSM_BYTES);
    cudaFuncSetAttribute(mma_gemm<false, false, false>,
                         cudaFuncAttributeMaxDynamicSharedMemorySize, DSM_BYTES);
    cudaFuncSetAttribute(mma_gemm<true, false, false>,
                         cudaFuncAttributeMaxDynamicSharedMemorySize, DSM_BYTES);
    cudaFuncSetAttribute(mma_gemm<false, true, false>,
                         cudaFuncAttributeMaxDynamicSharedMemorySize, DSM_BYTES);

    const long long sQKV = (long long)SS * DD;
    const long long sSco = (long long)SS * SS;
    const float scale = 0.03125f;     // 1024^-0.5

    dim3 tb(32, 8);

    // 0) split inputs: x and W^T
    const int xn4 = BB * SS * DD / 4;
    convert_split<<<(xn4 + 255) / 256, 256>>>(x, Xh, Xl, xn4);
    transpose_split<<<dim3(DD / 32, DD / 32, 1), tb>>>(Wq, WthQ, WtlQ, DD, DD, 0, 0);
    transpose_split<<<dim3(DD / 32, DD / 32, 1), tb>>>(Wk, WthK, WtlK, DD, DD, 0, 0);
    transpose_split<<<dim3(DD / 32, DD / 32, 1), tb>>>(Wv, WthV, WtlV, DD, DD, 0, 0);

    // 1) QKV projections (Q,K: split-bf16 epilogue; V: fp32 for transpose)
    dim3 gq(DD / TN, (BB * SS) / TM, 1);
    mma_gemm<false, false, true><<<gq, NTHREADS, DSM_BYTES>>>(
        Xh, Xl, DD, 0, WthQ, WtlQ, DD, 0, nullptr, Qh, Ql, DD, 0, DD, 1.0f);
    mma_gemm<false, false, true><<<gq, NTHREADS, DSM_BYTES>>>(
        Xh, Xl, DD, 0, WthK, WtlK, DD, 0, nullptr, Kh, Kl, DD, 0, DD, 1.0f);
    mma_gemm<false, false, false><<<gq, NTHREADS, DSM_BYTES>>>(
        Xh, Xl, DD, 0, WthV, WtlV, DD, 0, V, nullptr, nullptr, DD, 0, DD, 1.0f);

    // 2) V^T split per batch: [2048,1024] -> [1024,2048]
    transpose_split<<<dim3(DD / 32, SS / 32, BB), tb>>>(V, Vth, Vtl, SS, DD,
                                                        sQKV, sQKV);

    // 3) scores = scale * Q @ K^T (tiles touching the lower triangle only)
    dim3 gs(SS / TN, SS / TM, BB);
    mma_gemm<true, false, false><<<gs, NTHREADS, DSM_BYTES>>>(
        Qh, Ql, DD, sQKV, Kh, Kl, DD, sQKV, Sb, nullptr, nullptr, SS, sSco,
        DD, scale);

    // 4) causal softmax -> split-bf16 probs (+ zero-fill to 128 boundary)
    softmax_causal<<<BB * SS, 256>>>(Sb, Ph, Pl);

    // 5) out = P @ V  (per-q-tile K range)
    dim3 gp(DD / TN, SS / TM, BB);
    mma_gemm<false, true, false><<<gp, NTHREADS, DSM_BYTES>>>(
        Ph, Pl, SS, sSco, Vth, Vtl, SS, sQKV, out, nullptr, nullptr, DD, sQKV,
        0, 1.0f);
}

// round 7
// speedup vs baseline: 4.1486x; 1.4361x over previous
#include <cuda_runtime.h>
#include <cstdint>
#include <math.h>

#define BB 4
#define SS 2048
#define DD 1024

#define TM 128
#define TN 64
#define TK 32
#define NTHREADS 256
#define STAGES 3
#define STAGE_BYTES 24576            // A fp32 16K | B fp32 8K
#define DSM_BYTES (STAGES * STAGE_BYTES + 1024)

// ---------------------------------------------------------------------------
// Scratch (__device__ globals: allocation-guard-safe). All values stored as
// fp32 whose mantissas are pre-rounded to tf32 (RNA) by their producers.
// ---------------------------------------------------------------------------
__device__ float g_X [(size_t)BB * SS * DD];          // x (tf32)      32 MB
__device__ float g_Wt[3][(size_t)DD * DD];            // W^T (tf32)    12 MB
__device__ float g_Q [(size_t)BB * SS * DD];          // Q (tf32)      32 MB
__device__ float g_K [(size_t)BB * SS * DD];          // K (tf32)      32 MB
__device__ float g_V [(size_t)BB * SS * DD];          // V fp32        32 MB
__device__ float g_Vt[(size_t)BB * SS * DD];          // V^T (tf32)    32 MB
__device__ float g_S [(size_t)BB * SS * SS];          // scores fp32   64 MB
__device__ float g_P [(size_t)BB * SS * SS];          // probs (tf32)  64 MB

// ---------------------------------------------------------------------------
// Helpers
// ---------------------------------------------------------------------------
__device__ __forceinline__ uint32_t smem_u32(const void* p) {
    uint32_t a;
    asm("{ .reg .u64 t; cvta.to.shared.u64 t, %1; cvt.u32.u64 %0, t; }"
        : "=r"(a) : "l"(p));
    return a;
}

__device__ __forceinline__ uint32_t tf32r(float f) {
    uint32_t r;
    asm("cvt.rna.tf32.f32 %0, %1;" : "=r"(r) : "f"(f));
    return r;
}

#define LDSM4(r, a)                                                        \
    asm volatile("ldmatrix.sync.aligned.m8n8.x4.shared.b16 "               \
                 "{%0,%1,%2,%3}, [%4];"                                    \
                 : "=r"((r)[0]), "=r"((r)[1]), "=r"((r)[2]), "=r"((r)[3])  \
                 : "r"(a))

#define MMATF32(d, a, b0, b1)                                              \
    asm volatile("mma.sync.aligned.m16n8k8.row.col.f32.tf32.tf32.f32 "     \
                 "{%0,%1,%2,%3},{%4,%5,%6,%7},{%8,%9},{%0,%1,%2,%3};"      \
                 : "+f"((d)[0]), "+f"((d)[1]), "+f"((d)[2]), "+f"((d)[3])  \
                 : "r"((a)[0]), "r"((a)[1]), "r"((a)[2]), "r"((a)[3]),     \
                   "r"(b0), "r"(b1))

#define CPA16(dst, src)                                                    \
    asm volatile("cp.async.cg.shared.global [%0], [%1], 16;"               \
                 :: "r"(dst), "l"(src))
#define CPA_COMMIT()  asm volatile("cp.async.commit_group;" ::: "memory")
#define CPA_WAIT1()   asm volatile("cp.async.wait_group 1;" ::: "memory")

// ---------------------------------------------------------------------------
// Single-pass tf32 mma.sync GEMM. CTA 128x64, 3-stage cp.async, 3 CTAs/SM.
//   C[m,n] = alpha * sum_k A[m,k] * B[n,k]   (fp32/tf32, B stored K-major)
//   Warp grid 4m x 2n, warp tile 32x32.
//   TRI : skip tiles fully above the diagonal; PERQ: K limit = (by+1)*TM
//   ROUND: round output to tf32 (for Q/K, which feed later MMAs)
// SMEM tile rows are 128 B (32 fp32); SW128 swizzle (XOR bits[6:4] w/ row[2:0]).
// ---------------------------------------------------------------------------
template<bool TRI, bool PERQ, bool ROUND>
__global__ void __launch_bounds__(NTHREADS, 3)
mma_gemm(const float* __restrict__ A, int lda, long long sA,
         const float* __restrict__ B, int ldb, long long sB,
         float* __restrict__ C, int ldc, long long sC,
         int Kfull, float alpha)
{
    const int m0 = blockIdx.y * TM;
    const int n0 = blockIdx.x * TN;
    if (TRI && n0 > m0 + TM - 1) return;

    extern __shared__ char dsm[];
    const uint32_t sbase = (smem_u32(dsm) + 1023u) & ~1023u;

    const long long z = blockIdx.z;
    A += sA * z; B += sB * z;

    const int Klim = PERQ ? (int)(blockIdx.y + 1) * TM : Kfull;
    const int KB = Klim / TK;

    const int tid  = threadIdx.x;
    const int lane = tid & 31;
    const int wid  = tid >> 5;
    const int wm = (wid & 3) * 32;        // warp m offset
    const int wn = (wid >> 2) * 32;       // warp n offset

    // cp.async: rows of 128 B (8 x 16B chunks). A: 128 rows (4 tasks/thread,
    // rows arow+{0,32,64,96}); B: 64 rows (2 tasks, rows arow+{0,32}).
    const int arow = tid >> 3, cu = tid & 7;
    const uint32_t aoffs =
        ((uint32_t)arow * 128u + (uint32_t)cu * 16u) ^ (((uint32_t)(arow & 7)) << 4);
    // (row+32k) & 7 == row & 7, so task i's smem offset = aoffs + i*4096.
    const float* gA = A + (long long)(m0 + arow) * lda + cu * 4;
    const float* gB = B + (long long)(n0 + arow) * ldb + cu * 4;
    const long long a32 = (long long)32 * lda;
    const long long b32 = (long long)32 * ldb;

    // ldmatrix fragment addresses (row part, swizzled; column XORed per kblk)
    const int fr = lane & 15;
    const uint32_t hb = (uint32_t)(lane >> 4) * 16u;
    uint32_t aSw[2], bSw[2];
#pragma unroll
    for (int mf = 0; mf < 2; mf++) {
        int row = wm + 16 * mf + fr;
        aSw[mf] = (uint32_t)row * 128u ^ (((uint32_t)(row & 7)) << 4);
    }
#pragma unroll
    for (int g = 0; g < 2; g++) {
        int row = wn + 16 * g + fr;
        bSw[g] = 16384u + ((uint32_t)row * 128u ^ (((uint32_t)(row & 7)) << 4));
    }

    float acc[2][4][4];
#pragma unroll
    for (int mf = 0; mf < 2; mf++)
#pragma unroll
        for (int nf = 0; nf < 4; nf++)
#pragma unroll
            for (int j = 0; j < 4; j++) acc[mf][nf][j] = 0.0f;

#define ISSUE_STAGE(sidx, k0)                                              \
    do {                                                                   \
        const uint32_t sb_ = sbase + (uint32_t)(sidx) * STAGE_BYTES;       \
        CPA16(sb_ + aoffs,          gA + (k0));                            \
        CPA16(sb_ + aoffs +  4096u, gA + (k0) + a32);                      \
        CPA16(sb_ + aoffs +  8192u, gA + (k0) + 2 * a32);                  \
        CPA16(sb_ + aoffs + 12288u, gA + (k0) + 3 * a32);                  \
        CPA16(sb_ + 16384u + aoffs,          gB + (k0));                   \
        CPA16(sb_ + 16384u + aoffs + 4096u,  gB + (k0) + b32);             \
    } while (0)

    // ---- prologue: stages 0..1 ----
#pragma unroll
    for (int s = 0; s < STAGES - 1; s++) {
        if (s < KB) ISSUE_STAGE(s, s * TK);
        CPA_COMMIT();
    }

    int sidx_c = 0;
    int sidx_w = STAGES - 1;
    for (int kb = 0; kb < KB; kb++) {
        CPA_WAIT1();
        __syncthreads();

        if (kb + STAGES - 1 < KB)
            ISSUE_STAGE(sidx_w, (kb + STAGES - 1) * TK);
        CPA_COMMIT();
        if (++sidx_w == STAGES) sidx_w = 0;

        const uint32_t buf = sbase + (uint32_t)sidx_c * STAGE_BYTES;
        if (++sidx_c == STAGES) sidx_c = 0;

#pragma unroll
        for (int kblk = 0; kblk < 4; kblk++) {            // 4 x k8 per k-block
            const uint32_t kc = (uint32_t)(kblk * 32) + hb;
            uint32_t a[2][4], b[2][4];
            LDSM4(a[0], buf + (aSw[0] ^ kc));
            LDSM4(a[1], buf + (aSw[1] ^ kc));
            LDSM4(b[0], buf + (bSw[0] ^ kc));
            LDSM4(b[1], buf + (bSw[1] ^ kc));
            // 16 independent MMAs (all distinct accumulators)
#pragma unroll
            for (int mf = 0; mf < 2; mf++)
#pragma unroll
                for (int g = 0; g < 2; g++)
#pragma unroll
                    for (int s = 0; s < 2; s++)
                        MMATF32(acc[mf][2 * g + s], a[mf], b[g][s], b[g][s + 2]);
        }
    }
#undef ISSUE_STAGE

    // ---- epilogue ----
    const int gq = lane >> 2, t = lane & 3;
    C += sC * z;
#pragma unroll
    for (int mf = 0; mf < 2; mf++) {
#pragma unroll
        for (int nf = 0; nf < 4; nf++) {
            const int r0  = m0 + wm + 16 * mf + gq;
            const int col = n0 + wn + 8 * nf + 2 * t;
            float v0 = acc[mf][nf][0] * alpha;
            float v1 = acc[mf][nf][1] * alpha;
            float v2 = acc[mf][nf][2] * alpha;
            float v3 = acc[mf][nf][3] * alpha;
            if (ROUND) {
                v0 = __uint_as_float(tf32r(v0));
                v1 = __uint_as_float(tf32r(v1));
                v2 = __uint_as_float(tf32r(v2));
                v3 = __uint_as_float(tf32r(v3));
            }
            float2 o0, o1;
            o0.x = v0; o0.y = v1; o1.x = v2; o1.y = v3;
            *reinterpret_cast<float2*>(C + (long long)r0 * ldc + col)       = o0;
            *reinterpret_cast<float2*>(C + (long long)(r0 + 8) * ldc + col) = o1;
        }
    }
}

// ---------------------------------------------------------------------------
// fp32 -> tf32-rounded fp32 elementwise (vectorized x4)
// ---------------------------------------------------------------------------
__global__ void __launch_bounds__(256)
convert_tf32(const float* __restrict__ in, float* __restrict__ out, int n4)
{
    int i = blockIdx.x * 256 + threadIdx.x;
    if (i >= n4) return;
    float4 v = reinterpret_cast<const float4*>(in)[i];
    v.x = __uint_as_float(tf32r(v.x));
    v.y = __uint_as_float(tf32r(v.y));
    v.z = __uint_as_float(tf32r(v.z));
    v.w = __uint_as_float(tf32r(v.w));
    reinterpret_cast<float4*>(out)[i] = v;
}

// ---------------------------------------------------------------------------
// fp32 [R x C] -> transposed tf32-rounded fp32 [C x R] (per-z batch)
// ---------------------------------------------------------------------------
__global__ void __launch_bounds__(256)
transpose_tf32(const float* __restrict__ in, float* __restrict__ out,
               int R, int C, long long sIn, long long sOut)
{
    __shared__ float t[32][33];
    in  += sIn * blockIdx.z;
    out += sOut * blockIdx.z;
    const int c0 = blockIdx.x * 32, r0 = blockIdx.y * 32;
#pragma unroll
    for (int j = threadIdx.y; j < 32; j += 8)
        t[j][threadIdx.x] = in[(long long)(r0 + j) * C + c0 + threadIdx.x];
    __syncthreads();
#pragma unroll
    for (int j = threadIdx.y; j < 32; j += 8)
        out[(long long)(c0 + j) * R + r0 + threadIdx.x] =
            __uint_as_float(tf32r(t[threadIdx.x][j]));
}

// ---------------------------------------------------------------------------
// Causal row softmax: fp32 scores -> tf32-rounded probs; zero-fill to the
// 128-aligned block end so P@V needs no masking.
// ---------------------------------------------------------------------------
__global__ void __launch_bounds__(256)
softmax_causal(const float* __restrict__ S, float* __restrict__ P)
{
    const int row = blockIdx.x;          // b*S + q
    const int q   = row & (SS - 1);
    const int limit = ((q >> 7) + 1) << 7;
    const float* p = S + (long long)row * SS;
    float* po = P + (long long)row * SS;

    const int tid = threadIdx.x;
    float v[8];
    float mx = -INFINITY;
#pragma unroll
    for (int i = 0; i < 8; i++) {
        int idx = i * 256 + tid;
        v[i] = (idx <= q) ? p[idx] : -INFINITY;
        mx = fmaxf(mx, v[i]);
    }

    __shared__ float red[256];
    red[tid] = mx;
    __syncthreads();
#pragma unroll
    for (int s = 128; s > 0; s >>= 1) {
        if (tid < s) red[tid] = fmaxf(red[tid], red[tid + s]);
        __syncthreads();
    }
    mx = red[0];
    __syncthreads();

    float e[8];
    float sum = 0.0f;
#pragma unroll
    for (int i = 0; i < 8; i++) {
        e[i] = __expf(v[i] - mx);
        sum += e[i];
    }
    red[tid] = sum;
    __syncthreads();
#pragma unroll
    for (int s = 128; s > 0; s >>= 1) {
        if (tid < s) red[tid] += red[tid + s];
        __syncthreads();
    }
    const float inv = 1.0f / red[0];

#pragma unroll
    for (int i = 0; i < 8; i++) {
        int idx = i * 256 + tid;
        if (idx <= q)          po[idx] = __uint_as_float(tf32r(e[i] * inv));
        else if (idx < limit)  po[idx] = 0.0f;
    }
}

// ---------------------------------------------------------------------------
// Launch sequence (graph-capturable: kernel launches only)
// ---------------------------------------------------------------------------
extern "C" void kernel_launch(void* const* d_in, const int* in_sizes, int n_in,
                              void* d_out, int out_size)
{
    const float* x  = (const float*)d_in[0];
    const float* Wq = (const float*)d_in[1];
    const float* Wk = (const float*)d_in[2];
    const float* Wv = (const float*)d_in[3];
    float* out = (float*)d_out;

    float *X, *Wt, *Q, *K, *V, *Vt, *Sb, *P;
    cudaGetSymbolAddress((void**)&X,  g_X);
    cudaGetSymbolAddress((void**)&Wt, g_Wt);
    cudaGetSymbolAddress((void**)&Q,  g_Q);
    cudaGetSymbolAddress((void**)&K,  g_K);
    cudaGetSymbolAddress((void**)&V,  g_V);
    cudaGetSymbolAddress((void**)&Vt, g_Vt);
    cudaGetSymbolAddress((void**)&Sb, g_S);
    cudaGetSymbolAddress((void**)&P,  g_P);

    const size_t wsz = (size_t)DD * DD;
    float *Wt0 = Wt, *Wt1 = Wt + wsz, *Wt2 = Wt + 2 * wsz;

    cudaFuncSetAttribute(mma_gemm<false, false, true>,
                         cudaFuncAttributeMaxDynamicSharedMemorySize, DSM_BYTES);
    cudaFuncSetAttribute(mma_gemm<false, false, false>,
                         cudaFuncAttributeMaxDynamicSharedMemorySize, DSM_BYTES);
    cudaFuncSetAttribute(mma_gemm<true, false, false>,
                         cudaFuncAttributeMaxDynamicSharedMemorySize, DSM_BYTES);
    cudaFuncSetAttribute(mma_gemm<false, true, false>,
                         cudaFuncAttributeMaxDynamicSharedMemorySize, DSM_BYTES);

    const long long sQKV = (long long)SS * DD;
    const long long sSco = (long long)SS * SS;
    const float scale = 0.03125f;     // 1024^-0.5

    dim3 tb(32, 8);

    // 0) round x to tf32; W^T (K-major, tf32)
    const int xn4 = BB * SS * DD / 4;
    convert_tf32<<<(xn4 + 255) / 256, 256>>>(x, X, xn4);
    transpose_tf32<<<dim3(DD / 32, DD / 32, 1), tb>>>(Wq, Wt0, DD, DD, 0, 0);
    transpose_tf32<<<dim3(DD / 32, DD / 32, 1), tb>>>(Wk, Wt1, DD, DD, 0, 0);
    transpose_tf32<<<dim3(DD / 32, DD / 32, 1), tb>>>(Wv, Wt2, DD, DD, 0, 0);

    // 1) QKV projections (Q,K rounded to tf32; V plain fp32 for transpose)
    dim3 gq(DD / TN, (BB * SS) / TM, 1);
    mma_gemm<false, false, true><<<gq, NTHREADS, DSM_BYTES>>>(
        X, DD, 0, Wt0, DD, 0, Q, DD, 0, DD, 1.0f);
    mma_gemm<false, false, true><<<gq, NTHREADS, DSM_BYTES>>>(
        X, DD, 0, Wt1, DD, 0, K, DD, 0, DD, 1.0f);
    mma_gemm<false, false, false><<<gq, NTHREADS, DSM_BYTES>>>(
        X, DD, 0, Wt2, DD, 0, V, DD, 0, DD, 1.0f);

    // 2) V^T per batch (rounds to tf32): [2048,1024] -> [1024,2048]
    transpose_tf32<<<dim3(DD / 32, SS / 32, BB), tb>>>(V, Vt, SS, DD, sQKV, sQKV);

    // 3) scores = scale * Q @ K^T (tiles touching the lower triangle only)
    dim3 gs(SS / TN, SS / TM, BB);
    mma_gemm<true, false, false><<<gs, NTHREADS, DSM_BYTES>>>(
        Q, DD, sQKV, K, DD, sQKV, Sb, SS, sSco, DD, scale);

    // 4) causal softmax -> tf32 probs (+ zero-fill to 128 boundary)
    softmax_causal<<<BB * SS, 256>>>(Sb, P);

    // 5) out = P @ V  (per-q-tile K range)
    dim3 gp(DD / TN, SS / TM, BB);
    mma_gemm<false, true, false><<<gp, NTHREADS, DSM_BYTES>>>(
        P, SS, sSco, Vt, SS, sQKV, out, DD, sQKV, 0, 1.0f);
}